// round 1
// baseline (speedup 1.0000x reference)
#include <cuda_runtime.h>
#include <math.h>

// Problem constants
#define BATCH  32
#define SEQ    480
#define DIMN   1024
#define HEADS  16
#define HD     64
#define MROWS  (BATCH * SEQ)   // 15360
#define ATTN_SCALE 0.125f      // 64^-0.5

// Scratch (device globals — allocation-free)
__device__ float g_QP[(size_t)MROWS * DIMN];
__device__ float g_KP[(size_t)MROWS * DIMN];
__device__ float g_VP[(size_t)MROWS * DIMN];
__device__ float g_O [(size_t)MROWS * DIMN];

// ---------------------------------------------------------------------------
// Generic GEMM: C[M][1024] = A[M][1024] @ W[1024][1024]^T (+ bias)
// BM=BN=64, BK=16, 256 threads, 4x4 register tile per thread.
// M=15360, K=N=1024 all divisible by tile dims -> no bounds checks.
// ---------------------------------------------------------------------------
template <bool BIAS>
__global__ __launch_bounds__(256)
void gemm_abT_kernel(const float* __restrict__ A,
                     const float* __restrict__ W,
                     const float* __restrict__ bias,
                     float* __restrict__ C)
{
    __shared__ float As[16][68];   // [k][m], padded
    __shared__ float Bs[16][68];   // [k][n], padded

    const int tid = threadIdx.x;
    const int tx  = tid & 15;
    const int ty  = tid >> 4;
    const int m0  = blockIdx.x * 64;
    const int n0  = blockIdx.y * 64;

    // loader mapping: each thread loads one float4 per tile per matrix
    const int lr = tid >> 2;          // 0..63 (tile row)
    const int lc = (tid & 3) << 2;    // 0,4,8,12 (k-offset)

    const float* Ap = A + (size_t)(m0 + lr) * DIMN + lc;
    const float* Wp = W + (size_t)(n0 + lr) * DIMN + lc;

    float acc[4][4] = {};

    for (int k0 = 0; k0 < DIMN; k0 += 16) {
        float4 av = *(const float4*)(Ap + k0);
        float4 wv = *(const float4*)(Wp + k0);
        As[lc + 0][lr] = av.x; As[lc + 1][lr] = av.y;
        As[lc + 2][lr] = av.z; As[lc + 3][lr] = av.w;
        Bs[lc + 0][lr] = wv.x; Bs[lc + 1][lr] = wv.y;
        Bs[lc + 2][lr] = wv.z; Bs[lc + 3][lr] = wv.w;
        __syncthreads();

#pragma unroll
        for (int kk = 0; kk < 16; kk++) {
            float4 a4 = *(const float4*)&As[kk][ty << 2];
            float4 b4 = *(const float4*)&Bs[kk][tx << 2];
            float ar[4] = {a4.x, a4.y, a4.z, a4.w};
            float br[4] = {b4.x, b4.y, b4.z, b4.w};
#pragma unroll
            for (int i = 0; i < 4; i++)
#pragma unroll
                for (int j = 0; j < 4; j++)
                    acc[i][j] = fmaf(ar[i], br[j], acc[i][j]);
        }
        __syncthreads();
    }

    float bv[4] = {0.f, 0.f, 0.f, 0.f};
    if (BIAS) {
#pragma unroll
        for (int j = 0; j < 4; j++) bv[j] = bias[n0 + (tx << 2) + j];
    }
#pragma unroll
    for (int i = 0; i < 4; i++) {
        float4 o;
        o.x = acc[i][0] + bv[0];
        o.y = acc[i][1] + bv[1];
        o.z = acc[i][2] + bv[2];
        o.w = acc[i][3] + bv[3];
        *(float4*)(C + (size_t)(m0 + (ty << 2) + i) * DIMN + n0 + (tx << 2)) = o;
    }
}

// ---------------------------------------------------------------------------
// Flash-style fused attention per (b, h, 64-query-tile).
// Online softmax over 8 key tiles of 64 (last tile half-valid, masked).
// smem: Qs/Ks transposed [d][row] for float4 fragment loads; Vs natural;
//       Ps [qrow][key] staged for the P@V GEMM.
// ---------------------------------------------------------------------------
__global__ __launch_bounds__(256)
void attn_kernel(const float* __restrict__ pe,
                 const float* __restrict__ QP,
                 const float* __restrict__ KP,
                 const float* __restrict__ VP,
                 float* __restrict__ O)
{
    extern __shared__ float sm[];
    float (*Qs)[68] = (float(*)[68])(sm);                // [d][qrow]
    float (*Ks)[68] = (float(*)[68])(sm + 1 * 64 * 68);  // [d][krow]
    float (*Vs)[68] = (float(*)[68])(sm + 2 * 64 * 68);  // [krow][d]
    float (*Ps)[68] = (float(*)[68])(sm + 3 * 64 * 68);  // [qrow][krow]

    const int tid = threadIdx.x;
    const int tx  = tid & 15;
    const int ty  = tid >> 4;
    const int qt  = blockIdx.x;          // 0..7
    const int bh  = blockIdx.y;          // 0..511
    const int b   = bh >> 4;
    const int h   = bh & 15;
    const int q0  = qt * 64;

    const int lr = tid >> 2;             // tile row for loads
    const int cg = (tid & 3) << 4;       // 16-col group

    // Load Q tile (transposed into smem), zero-fill OOB rows
    {
        const int qr = q0 + lr;
        const bool v = (qr < SEQ);
        const float* src = QP + ((size_t)(b * SEQ + (v ? qr : 0))) * DIMN + h * HD + cg;
#pragma unroll
        for (int u = 0; u < 4; u++) {
            float4 f = v ? *(const float4*)(src + 4 * u) : make_float4(0.f, 0.f, 0.f, 0.f);
            Qs[cg + 4 * u + 0][lr] = f.x;
            Qs[cg + 4 * u + 1][lr] = f.y;
            Qs[cg + 4 * u + 2][lr] = f.z;
            Qs[cg + 4 * u + 3][lr] = f.w;
        }
    }

    float oacc[4][4] = {};
    float mrow[4] = {-INFINITY, -INFINITY, -INFINITY, -INFINITY};
    float lsum[4] = {};

    for (int kb = 0; kb < 8; kb++) {
        const int k0 = kb * 64;
        __syncthreads();   // previous iteration's GEMM2 done with Ks/Vs/Ps
        // Load K (transposed) and V (natural), zero-fill OOB rows
        {
            const int kr = k0 + lr;
            const bool v = (kr < SEQ);
            const float* ks = KP + ((size_t)(b * SEQ + (v ? kr : 0))) * DIMN + h * HD + cg;
            const float* vs = VP + ((size_t)(b * SEQ + (v ? kr : 0))) * DIMN + h * HD + cg;
#pragma unroll
            for (int u = 0; u < 4; u++) {
                float4 fk = v ? *(const float4*)(ks + 4 * u) : make_float4(0.f, 0.f, 0.f, 0.f);
                float4 fv = v ? *(const float4*)(vs + 4 * u) : make_float4(0.f, 0.f, 0.f, 0.f);
                Ks[cg + 4 * u + 0][lr] = fk.x;
                Ks[cg + 4 * u + 1][lr] = fk.y;
                Ks[cg + 4 * u + 2][lr] = fk.z;
                Ks[cg + 4 * u + 3][lr] = fk.w;
                *(float4*)&Vs[lr][cg + 4 * u] = fv;
            }
        }
        __syncthreads();

        // S = Q @ K^T (64x64x64)
        float s[4][4] = {};
#pragma unroll 8
        for (int kk = 0; kk < 64; kk++) {
            float4 a4 = *(const float4*)&Qs[kk][ty << 2];
            float4 b4 = *(const float4*)&Ks[kk][tx << 2];
            float ar[4] = {a4.x, a4.y, a4.z, a4.w};
            float br[4] = {b4.x, b4.y, b4.z, b4.w};
#pragma unroll
            for (int i = 0; i < 4; i++)
#pragma unroll
                for (int j = 0; j < 4; j++)
                    s[i][j] = fmaf(ar[i], br[j], s[i][j]);
        }

        // scale + positional bias + key masking
#pragma unroll
        for (int i = 0; i < 4; i++) {
            const int qr = q0 + (ty << 2) + i;
#pragma unroll
            for (int j = 0; j < 4; j++) {
                const int kc = k0 + (tx << 2) + j;
                float sv = s[i][j] * ATTN_SCALE;
                if (kc < SEQ) {
                    if (qr < SEQ) sv += pe[qr * SEQ + kc];
                } else {
                    sv = -1e30f;
                }
                s[i][j] = sv;
            }
        }

        // online softmax update (row stats reduced across 16 tx lanes)
        float p[4][4];
#pragma unroll
        for (int i = 0; i < 4; i++) {
            float rm = fmaxf(fmaxf(s[i][0], s[i][1]), fmaxf(s[i][2], s[i][3]));
#pragma unroll
            for (int off = 8; off; off >>= 1)
                rm = fmaxf(rm, __shfl_xor_sync(0xffffffffu, rm, off));
            const float mnew = fmaxf(mrow[i], rm);
            const float fct  = __expf(mrow[i] - mnew);   // first iter: exp(-inf)=0
            mrow[i] = mnew;
            float sum = 0.f;
#pragma unroll
            for (int j = 0; j < 4; j++) {
                const float e = __expf(s[i][j] - mnew);
                p[i][j] = e;
                sum += e;
            }
#pragma unroll
            for (int off = 8; off; off >>= 1)
                sum += __shfl_xor_sync(0xffffffffu, sum, off);
            lsum[i] = lsum[i] * fct + sum;
#pragma unroll
            for (int j = 0; j < 4; j++) oacc[i][j] *= fct;
        }

        // stage P to smem
#pragma unroll
        for (int i = 0; i < 4; i++)
            *(float4*)&Ps[(ty << 2) + i][tx << 2] =
                make_float4(p[i][0], p[i][1], p[i][2], p[i][3]);
        __syncthreads();

        // O += P @ V (64x64x64)
#pragma unroll 8
        for (int kk = 0; kk < 64; kk++) {
            float4 b4 = *(const float4*)&Vs[kk][tx << 2];
#pragma unroll
            for (int i = 0; i < 4; i++) {
                const float a = Ps[(ty << 2) + i][kk];
                oacc[i][0] = fmaf(a, b4.x, oacc[i][0]);
                oacc[i][1] = fmaf(a, b4.y, oacc[i][1]);
                oacc[i][2] = fmaf(a, b4.z, oacc[i][2]);
                oacc[i][3] = fmaf(a, b4.w, oacc[i][3]);
            }
        }
    }

    // normalize + write
#pragma unroll
    for (int i = 0; i < 4; i++) {
        const int qr = q0 + (ty << 2) + i;
        if (qr < SEQ) {
            const float inv = 1.f / lsum[i];
            float4 o = make_float4(oacc[i][0] * inv, oacc[i][1] * inv,
                                   oacc[i][2] * inv, oacc[i][3] * inv);
            *(float4*)(O + ((size_t)(b * SEQ + qr)) * DIMN + h * HD + (tx << 2)) = o;
        }
    }
}

// ---------------------------------------------------------------------------
extern "C" void kernel_launch(void* const* d_in, const int* in_sizes, int n_in,
                              void* d_out, int out_size)
{
    const float* q  = (const float*)d_in[0];
    const float* Wq = (const float*)d_in[1];
    const float* Wk = (const float*)d_in[2];
    const float* Wv = (const float*)d_in[3];
    const float* pe = (const float*)d_in[4];
    const float* Wo = (const float*)d_in[5];
    const float* bo = (const float*)d_in[6];
    float* out = (float*)d_out;

    float *QP, *KP, *VP, *O;
    cudaGetSymbolAddress((void**)&QP, g_QP);
    cudaGetSymbolAddress((void**)&KP, g_KP);
    cudaGetSymbolAddress((void**)&VP, g_VP);
    cudaGetSymbolAddress((void**)&O,  g_O);

    const int attn_smem = 4 * 64 * 68 * sizeof(float);   // 69632 B
    cudaFuncSetAttribute(attn_kernel,
                         cudaFuncAttributeMaxDynamicSharedMemorySize, attn_smem);

    dim3 ggrid(MROWS / 64, DIMN / 64);   // (240, 16)

    gemm_abT_kernel<false><<<ggrid, 256>>>(q, Wq, nullptr, QP);
    gemm_abT_kernel<false><<<ggrid, 256>>>(q, Wk, nullptr, KP);
    gemm_abT_kernel<false><<<ggrid, 256>>>(q, Wv, nullptr, VP);

    attn_kernel<<<dim3(8, BATCH * HEADS), 256, attn_smem>>>(pe, QP, KP, VP, O);

    gemm_abT_kernel<true><<<ggrid, 256>>>(O, Wo, bo, out);
}

// round 3
// speedup vs baseline: 2.1274x; 2.1274x over previous
#include <cuda_runtime.h>
#include <cuda_fp16.h>
#include <cstdint>
#include <math.h>

// ---------------------------------------------------------------------------
// Problem constants
// ---------------------------------------------------------------------------
#define BATCH  32
#define SEQ    480
#define DIMN   1024
#define HEADS  16
#define HD     64
#define MROWS  (BATCH * SEQ)        // 15360
#define PLD    3072                 // fused QKV projection row stride
#define ATTN_SCALE 0.125f

// ---------------------------------------------------------------------------
// Device scratch (allocation-free)
// ---------------------------------------------------------------------------
__device__ float  g_P[(size_t)MROWS * PLD];          // fused QKV output (fp32)
__device__ __half g_qhi[(size_t)MROWS * DIMN];
__device__ __half g_qlo[(size_t)MROWS * DIMN];
__device__ __half g_Ohi[(size_t)MROWS * DIMN];
__device__ __half g_Olo[(size_t)MROWS * DIMN];
__device__ __half g_Wcat_hi[(size_t)PLD * DIMN];     // [Wq;Wk;Wv]
__device__ __half g_Wcat_lo[(size_t)PLD * DIMN];
__device__ __half g_Wo_hi[(size_t)DIMN * DIMN];
__device__ __half g_Wo_lo[(size_t)DIMN * DIMN];

// ---------------------------------------------------------------------------
// PTX helpers (sm_80-era, arch-portable: mma.sync / ldmatrix / cp.async)
// ---------------------------------------------------------------------------
__device__ __forceinline__ uint32_t smem_to_u32(const void* p) {
    uint32_t a;
    asm("{ .reg .u64 t; cvta.to.shared.u64 t, %1; cvt.u32.u64 %0, t; }"
        : "=r"(a) : "l"(p));
    return a;
}

__device__ __forceinline__ void mma16816(float* d, const uint32_t* a,
                                         const uint32_t* b) {
    asm volatile(
        "mma.sync.aligned.m16n8k16.row.col.f32.f16.f16.f32 "
        "{%0,%1,%2,%3}, {%4,%5,%6,%7}, {%8,%9}, {%0,%1,%2,%3};"
        : "+f"(d[0]), "+f"(d[1]), "+f"(d[2]), "+f"(d[3])
        : "r"(a[0]), "r"(a[1]), "r"(a[2]), "r"(a[3]),
          "r"(b[0]), "r"(b[1]));
}

__device__ __forceinline__ void ldsm_x4(uint32_t* r, uint32_t saddr) {
    asm volatile(
        "ldmatrix.sync.aligned.m8n8.x4.shared.b16 {%0,%1,%2,%3}, [%4];"
        : "=r"(r[0]), "=r"(r[1]), "=r"(r[2]), "=r"(r[3]) : "r"(saddr));
}

__device__ __forceinline__ void cp16(uint32_t s, const void* g) {
    asm volatile("cp.async.cg.shared.global [%0], [%1], 16;"
                 :: "r"(s), "l"(g));
}
#define CP_COMMIT() asm volatile("cp.async.commit_group;" ::: "memory")
#define CP_WAIT2()  asm volatile("cp.async.wait_group 2;"  ::: "memory")

// ---------------------------------------------------------------------------
// fp32 -> fp16 hi/lo split (float4 per thread)
// ---------------------------------------------------------------------------
__global__ __launch_bounds__(256)
void split_kernel(const float* __restrict__ x,
                  __half* __restrict__ hi,
                  __half* __restrict__ lo, int n)
{
    int i = (blockIdx.x * 256 + threadIdx.x) * 4;
    if (i >= n) return;
    float4 v = *(const float4*)(x + i);
    float vv[4] = {v.x, v.y, v.z, v.w};
    __half h[4], l[4];
#pragma unroll
    for (int j = 0; j < 4; j++) {
        h[j] = __float2half_rn(vv[j]);
        l[j] = __float2half_rn(vv[j] - __half2float(h[j]));
    }
    __half2* hp = (__half2*)(hi + i);
    __half2* lp = (__half2*)(lo + i);
    hp[0] = __half2{h[0], h[1]};
    hp[1] = __half2{h[2], h[3]};
    lp[0] = __half2{l[0], l[1]};
    lp[1] = __half2{l[2], l[3]};
}

// ---------------------------------------------------------------------------
// fp16x3 tensor-core GEMM: C[M][N] = (Ahi+Alo) @ (Bhi+Blo)^T (+bias)
// A: [M,1024] row-major halves; B: [N,1024] row-major halves.
// CTA tile 128x128, BK=32, 3-stage cp.async pipeline, 256 threads.
// smem rows padded to 80B -> conflict-free ldmatrix without swizzle.
// ---------------------------------------------------------------------------
#define ASTR   80                       // bytes per 32-half row
#define TILE_B (128 * ASTR)             // 10240 per tile
#define OFF_AH 0
#define OFF_AL (1 * TILE_B)
#define OFF_BH (2 * TILE_B)
#define OFF_BL (3 * TILE_B)
#define BUF_B  (4 * TILE_B)             // 40960 per stage
#define GEMM_SMEM (3 * BUF_B)           // 122880

template <bool BIAS>
__global__ __launch_bounds__(256)
void gemm_f16x3(const __half* __restrict__ Ahi,
                const __half* __restrict__ Alo,
                const __half* __restrict__ Bhi,
                const __half* __restrict__ Blo,
                const float* __restrict__ bias,
                float* __restrict__ C, int ldc)
{
    extern __shared__ __align__(128) char smem[];
    const uint32_t sb = smem_to_u32(smem);

    const int tid  = threadIdx.x;
    const int lane = tid & 31;
    const int wid  = tid >> 5;
    const int wm   = wid >> 1;           // 0..3 -> 32-row slice
    const int wn   = wid & 1;            // 0..1 -> 64-col slice
    const int m0   = blockIdx.y * 128;
    const int n0   = blockIdx.x * 128;

    // loader mapping: id -> (row, 16B-chunk)
    const int lrow0 = tid >> 2;          // rows 0..63   (id = tid)
    const int lrow1 = (tid + 256) >> 2;  // rows 64..127 (id = tid+256)
    const int lch   = (tid & 3) * 8;     // halves offset within 32-half slab

    const __half* gAh = Ahi + (size_t)(m0 + lrow0) * DIMN + lch;
    const __half* gAl = Alo + (size_t)(m0 + lrow0) * DIMN + lch;
    const __half* gBh = Bhi + (size_t)(n0 + lrow0) * DIMN + lch;
    const __half* gBl = Blo + (size_t)(n0 + lrow0) * DIMN + lch;
    const size_t rstep = (size_t)64 * DIMN;
    const uint32_t s0 = (uint32_t)(lrow0 * ASTR + (tid & 3) * 16);
    const uint32_t s1 = (uint32_t)(lrow1 * ASTR + (tid & 3) * 16);

    // ldmatrix lane addressing
    const uint32_t aByte = (uint32_t)((wm * 32 + (lane & 15)) * ASTR +
                                      (lane >> 4) * 16);
    const uint32_t bByte = (uint32_t)((wn * 64 + ((lane >> 4) << 3) + (lane & 7)) * ASTR +
                                      ((lane >> 3) & 1) * 16);

    float acc[2][8][4];
#pragma unroll
    for (int i = 0; i < 2; i++)
#pragma unroll
        for (int j = 0; j < 8; j++)
#pragma unroll
            for (int c = 0; c < 4; c++) acc[i][j][c] = 0.f;

    // ---- preload 3 stages ----
#pragma unroll
    for (int st = 0; st < 3; st++) {
        const int k0 = st * 32;
        const uint32_t base = sb + st * BUF_B;
        cp16(base + OFF_AH + s0, gAh + k0);
        cp16(base + OFF_AH + s1, gAh + k0 + rstep);
        cp16(base + OFF_AL + s0, gAl + k0);
        cp16(base + OFF_AL + s1, gAl + k0 + rstep);
        cp16(base + OFF_BH + s0, gBh + k0);
        cp16(base + OFF_BH + s1, gBh + k0 + rstep);
        cp16(base + OFF_BL + s0, gBl + k0);
        cp16(base + OFF_BL + s1, gBl + k0 + rstep);
        CP_COMMIT();
    }

    for (int s = 0; s < 32; s++) {
        CP_WAIT2();
        __syncthreads();

        const uint32_t base = sb + (s % 3) * BUF_B;

#pragma unroll
        for (int kk = 0; kk < 2; kk++) {
            uint32_t ah[2][4], al[2][4];
#pragma unroll
            for (int mi = 0; mi < 2; mi++) {
                ldsm_x4(ah[mi], base + OFF_AH + aByte + mi * 16 * ASTR + kk * 32);
                ldsm_x4(al[mi], base + OFF_AL + aByte + mi * 16 * ASTR + kk * 32);
            }
            uint32_t bh[4][4], bl[4][4];
#pragma unroll
            for (int bn = 0; bn < 4; bn++) {
                ldsm_x4(bh[bn], base + OFF_BH + bByte + bn * 16 * ASTR + kk * 32);
                ldsm_x4(bl[bn], base + OFF_BL + bByte + bn * 16 * ASTR + kk * 32);
            }
#pragma unroll
            for (int mi = 0; mi < 2; mi++)
#pragma unroll
                for (int ni = 0; ni < 8; ni++) {
                    const uint32_t* fh = &bh[ni >> 1][(ni & 1) * 2];
                    const uint32_t* fl = &bl[ni >> 1][(ni & 1) * 2];
                    mma16816(acc[mi][ni], ah[mi], fh);
                    mma16816(acc[mi][ni], ah[mi], fl);
                    mma16816(acc[mi][ni], al[mi], fh);
                }
        }

        __syncthreads();
        if (s + 3 < 32) {
            const int k0 = (s + 3) * 32;
            const uint32_t nb = sb + (s % 3) * BUF_B;
            cp16(nb + OFF_AH + s0, gAh + k0);
            cp16(nb + OFF_AH + s1, gAh + k0 + rstep);
            cp16(nb + OFF_AL + s0, gAl + k0);
            cp16(nb + OFF_AL + s1, gAl + k0 + rstep);
            cp16(nb + OFF_BH + s0, gBh + k0);
            cp16(nb + OFF_BH + s1, gBh + k0 + rstep);
            cp16(nb + OFF_BL + s0, gBl + k0);
            cp16(nb + OFF_BL + s1, gBl + k0 + rstep);
        }
        CP_COMMIT();
    }

    // ---- epilogue: direct float2 stores ----
#pragma unroll
    for (int mi = 0; mi < 2; mi++) {
        const int row = m0 + wm * 32 + mi * 16 + (lane >> 2);
#pragma unroll
        for (int ni = 0; ni < 8; ni++) {
            const int col = n0 + wn * 64 + ni * 8 + ((lane & 3) << 1);
            float b0 = 0.f, b1 = 0.f;
            if (BIAS) { b0 = bias[col]; b1 = bias[col + 1]; }
            float2 v0 = make_float2(acc[mi][ni][0] + b0, acc[mi][ni][1] + b1);
            float2 v1 = make_float2(acc[mi][ni][2] + b0, acc[mi][ni][3] + b1);
            *(float2*)(C + (size_t)row * ldc + col)       = v0;
            *(float2*)(C + (size_t)(row + 8) * ldc + col) = v1;
        }
    }
}

// ---------------------------------------------------------------------------
// Flash-style fp32 attention (reads fused P buffer, writes fp16 hi/lo O)
// ---------------------------------------------------------------------------
__global__ __launch_bounds__(256)
void attn_kernel(const float* __restrict__ pe,
                 const float* __restrict__ P,
                 __half* __restrict__ Ohi,
                 __half* __restrict__ Olo)
{
    extern __shared__ float sm[];
    float (*Qs)[68] = (float(*)[68])(sm);
    float (*Ks)[68] = (float(*)[68])(sm + 1 * 64 * 68);
    float (*Vs)[68] = (float(*)[68])(sm + 2 * 64 * 68);
    float (*Ps)[68] = (float(*)[68])(sm + 3 * 64 * 68);

    const int tid = threadIdx.x;
    const int tx  = tid & 15;
    const int ty  = tid >> 4;
    const int qt  = blockIdx.x;
    const int bh  = blockIdx.y;
    const int b   = bh >> 4;
    const int h   = bh & 15;
    const int q0  = qt * 64;

    const int lr = tid >> 2;
    const int cg = (tid & 3) << 4;

    {
        const int qr = q0 + lr;
        const bool v = (qr < SEQ);
        const float* src = P + (size_t)(b * SEQ + (v ? qr : 0)) * PLD + h * HD + cg;
#pragma unroll
        for (int u = 0; u < 4; u++) {
            float4 f = v ? *(const float4*)(src + 4 * u) : make_float4(0.f, 0.f, 0.f, 0.f);
            Qs[cg + 4 * u + 0][lr] = f.x;
            Qs[cg + 4 * u + 1][lr] = f.y;
            Qs[cg + 4 * u + 2][lr] = f.z;
            Qs[cg + 4 * u + 3][lr] = f.w;
        }
    }

    float oacc[4][4] = {};
    float mrow[4] = {-INFINITY, -INFINITY, -INFINITY, -INFINITY};
    float lsum[4] = {};

    for (int kb = 0; kb < 8; kb++) {
        const int k0 = kb * 64;
        __syncthreads();
        {
            const int kr = k0 + lr;
            const bool v = (kr < SEQ);
            const float* ks = P + (size_t)(b * SEQ + (v ? kr : 0)) * PLD + DIMN + h * HD + cg;
            const float* vs = P + (size_t)(b * SEQ + (v ? kr : 0)) * PLD + 2 * DIMN + h * HD + cg;
#pragma unroll
            for (int u = 0; u < 4; u++) {
                float4 fk = v ? *(const float4*)(ks + 4 * u) : make_float4(0.f, 0.f, 0.f, 0.f);
                float4 fv = v ? *(const float4*)(vs + 4 * u) : make_float4(0.f, 0.f, 0.f, 0.f);
                Ks[cg + 4 * u + 0][lr] = fk.x;
                Ks[cg + 4 * u + 1][lr] = fk.y;
                Ks[cg + 4 * u + 2][lr] = fk.z;
                Ks[cg + 4 * u + 3][lr] = fk.w;
                *(float4*)&Vs[lr][cg + 4 * u] = fv;
            }
        }
        __syncthreads();

        float s[4][4] = {};
#pragma unroll 8
        for (int kk = 0; kk < 64; kk++) {
            float4 a4 = *(const float4*)&Qs[kk][ty << 2];
            float4 b4 = *(const float4*)&Ks[kk][tx << 2];
            float ar[4] = {a4.x, a4.y, a4.z, a4.w};
            float br[4] = {b4.x, b4.y, b4.z, b4.w};
#pragma unroll
            for (int i = 0; i < 4; i++)
#pragma unroll
                for (int j = 0; j < 4; j++)
                    s[i][j] = fmaf(ar[i], br[j], s[i][j]);
        }

#pragma unroll
        for (int i = 0; i < 4; i++) {
            const int qr = q0 + (ty << 2) + i;
#pragma unroll
            for (int j = 0; j < 4; j++) {
                const int kc = k0 + (tx << 2) + j;
                float sv = s[i][j] * ATTN_SCALE;
                if (kc < SEQ) {
                    if (qr < SEQ) sv += pe[qr * SEQ + kc];
                } else {
                    sv = -1e30f;
                }
                s[i][j] = sv;
            }
        }

        float p[4][4];
#pragma unroll
        for (int i = 0; i < 4; i++) {
            float rm = fmaxf(fmaxf(s[i][0], s[i][1]), fmaxf(s[i][2], s[i][3]));
#pragma unroll
            for (int off = 8; off; off >>= 1)
                rm = fmaxf(rm, __shfl_xor_sync(0xffffffffu, rm, off));
            const float mnew = fmaxf(mrow[i], rm);
            const float fct  = __expf(mrow[i] - mnew);
            mrow[i] = mnew;
            float sum = 0.f;
#pragma unroll
            for (int j = 0; j < 4; j++) {
                const float e = __expf(s[i][j] - mnew);
                p[i][j] = e;
                sum += e;
            }
#pragma unroll
            for (int off = 8; off; off >>= 1)
                sum += __shfl_xor_sync(0xffffffffu, sum, off);
            lsum[i] = lsum[i] * fct + sum;
#pragma unroll
            for (int j = 0; j < 4; j++) oacc[i][j] *= fct;
        }

#pragma unroll
        for (int i = 0; i < 4; i++)
            *(float4*)&Ps[(ty << 2) + i][tx << 2] =
                make_float4(p[i][0], p[i][1], p[i][2], p[i][3]);
        __syncthreads();

#pragma unroll 8
        for (int kk = 0; kk < 64; kk++) {
            float4 b4 = *(const float4*)&Vs[kk][tx << 2];
#pragma unroll
            for (int i = 0; i < 4; i++) {
                const float a = Ps[(ty << 2) + i][kk];
                oacc[i][0] = fmaf(a, b4.x, oacc[i][0]);
                oacc[i][1] = fmaf(a, b4.y, oacc[i][1]);
                oacc[i][2] = fmaf(a, b4.z, oacc[i][2]);
                oacc[i][3] = fmaf(a, b4.w, oacc[i][3]);
            }
        }
    }

#pragma unroll
    for (int i = 0; i < 4; i++) {
        const int qr = q0 + (ty << 2) + i;
        if (qr < SEQ) {
            const float inv = 1.f / lsum[i];
            size_t idx = (size_t)(b * SEQ + qr) * DIMN + h * HD + (tx << 2);
            __half hv[4], lv[4];
#pragma unroll
            for (int j = 0; j < 4; j++) {
                float v = oacc[i][j] * inv;
                hv[j] = __float2half_rn(v);
                lv[j] = __float2half_rn(v - __half2float(hv[j]));
            }
            *(__half2*)(Ohi + idx)     = __half2{hv[0], hv[1]};
            *(__half2*)(Ohi + idx + 2) = __half2{hv[2], hv[3]};
            *(__half2*)(Olo + idx)     = __half2{lv[0], lv[1]};
            *(__half2*)(Olo + idx + 2) = __half2{lv[2], lv[3]};
        }
    }
}

// ---------------------------------------------------------------------------
extern "C" void kernel_launch(void* const* d_in, const int* in_sizes, int n_in,
                              void* d_out, int out_size)
{
    const float* q  = (const float*)d_in[0];
    const float* Wq = (const float*)d_in[1];
    const float* Wk = (const float*)d_in[2];
    const float* Wv = (const float*)d_in[3];
    const float* pe = (const float*)d_in[4];
    const float* Wo = (const float*)d_in[5];
    const float* bo = (const float*)d_in[6];
    float* out = (float*)d_out;

    float* P;
    __half *qhi, *qlo, *Ohi, *Olo, *Wch, *Wcl, *Woh, *Wol;
    cudaGetSymbolAddress((void**)&P,   g_P);
    cudaGetSymbolAddress((void**)&qhi, g_qhi);
    cudaGetSymbolAddress((void**)&qlo, g_qlo);
    cudaGetSymbolAddress((void**)&Ohi, g_Ohi);
    cudaGetSymbolAddress((void**)&Olo, g_Olo);
    cudaGetSymbolAddress((void**)&Wch, g_Wcat_hi);
    cudaGetSymbolAddress((void**)&Wcl, g_Wcat_lo);
    cudaGetSymbolAddress((void**)&Woh, g_Wo_hi);
    cudaGetSymbolAddress((void**)&Wol, g_Wo_lo);

    const int nq = MROWS * DIMN;      // 15,728,640
    const int nw = DIMN * DIMN;       // 1,048,576

    split_kernel<<<nq / 4 / 256, 256>>>(q, qhi, qlo, nq);
    split_kernel<<<nw / 4 / 256, 256>>>(Wq, Wch,          Wcl,          nw);
    split_kernel<<<nw / 4 / 256, 256>>>(Wk, Wch + nw,     Wcl + nw,     nw);
    split_kernel<<<nw / 4 / 256, 256>>>(Wv, Wch + 2 * nw, Wcl + 2 * nw, nw);
    split_kernel<<<nw / 4 / 256, 256>>>(Wo, Woh,          Wol,          nw);

    cudaFuncSetAttribute(gemm_f16x3<false>,
                         cudaFuncAttributeMaxDynamicSharedMemorySize, GEMM_SMEM);
    cudaFuncSetAttribute(gemm_f16x3<true>,
                         cudaFuncAttributeMaxDynamicSharedMemorySize, GEMM_SMEM);

    // Fused QKV projection: [15360,1024] x [3072,1024]^T -> g_P [15360,3072]
    gemm_f16x3<false><<<dim3(PLD / 128, MROWS / 128), 256, GEMM_SMEM>>>(
        qhi, qlo, Wch, Wcl, nullptr, P, PLD);

    const int attn_smem = 4 * 64 * 68 * sizeof(float);
    cudaFuncSetAttribute(attn_kernel,
                         cudaFuncAttributeMaxDynamicSharedMemorySize, attn_smem);
    attn_kernel<<<dim3(8, BATCH * HEADS), 256, attn_smem>>>(pe, P, Ohi, Olo);

    // Output projection: [15360,1024] x [1024,1024]^T + bo -> out
    gemm_f16x3<true><<<dim3(DIMN / 128, MROWS / 128), 256, GEMM_SMEM>>>(
        Ohi, Olo, Woh, Wol, bo, out, DIMN);
}

// round 4
// speedup vs baseline: 3.0125x; 1.4161x over previous
#include <cuda_runtime.h>
#include <cuda_fp16.h>
#include <cstdint>
#include <math.h>

// ---------------------------------------------------------------------------
// Problem constants
// ---------------------------------------------------------------------------
#define BATCH  32
#define SEQ    480
#define DIMN   1024
#define HEADS  16
#define HD     64
#define MROWS  (BATCH * SEQ)        // 15360
#define PLD    3072                 // fused QKV projection row stride
#define ATTN_SCALE 0.125f

// ---------------------------------------------------------------------------
// Device scratch (allocation-free)
// ---------------------------------------------------------------------------
__device__ __half g_QKVhi[(size_t)MROWS * PLD];
__device__ __half g_QKVlo[(size_t)MROWS * PLD];
__device__ __half g_qhi[(size_t)MROWS * DIMN];
__device__ __half g_qlo[(size_t)MROWS * DIMN];
__device__ __half g_Ohi[(size_t)MROWS * DIMN];
__device__ __half g_Olo[(size_t)MROWS * DIMN];
__device__ __half g_Wcat_hi[(size_t)PLD * DIMN];     // [Wq;Wk;Wv]
__device__ __half g_Wcat_lo[(size_t)PLD * DIMN];
__device__ __half g_Wo_hi[(size_t)DIMN * DIMN];
__device__ __half g_Wo_lo[(size_t)DIMN * DIMN];

// ---------------------------------------------------------------------------
// PTX helpers (sm_80-era, arch-portable: mma.sync / ldmatrix / cp.async)
// ---------------------------------------------------------------------------
__device__ __forceinline__ uint32_t smem_to_u32(const void* p) {
    uint32_t a;
    asm("{ .reg .u64 t; cvta.to.shared.u64 t, %1; cvt.u32.u64 %0, t; }"
        : "=r"(a) : "l"(p));
    return a;
}

__device__ __forceinline__ void mma16816(float* d, const uint32_t* a,
                                         const uint32_t* b) {
    asm volatile(
        "mma.sync.aligned.m16n8k16.row.col.f32.f16.f16.f32 "
        "{%0,%1,%2,%3}, {%4,%5,%6,%7}, {%8,%9}, {%0,%1,%2,%3};"
        : "+f"(d[0]), "+f"(d[1]), "+f"(d[2]), "+f"(d[3])
        : "r"(a[0]), "r"(a[1]), "r"(a[2]), "r"(a[3]),
          "r"(b[0]), "r"(b[1]));
}

__device__ __forceinline__ void ldsm_x4(uint32_t* r, uint32_t saddr) {
    asm volatile(
        "ldmatrix.sync.aligned.m8n8.x4.shared.b16 {%0,%1,%2,%3}, [%4];"
        : "=r"(r[0]), "=r"(r[1]), "=r"(r[2]), "=r"(r[3]) : "r"(saddr));
}

__device__ __forceinline__ void ldsm_x4_t(uint32_t* r, uint32_t saddr) {
    asm volatile(
        "ldmatrix.sync.aligned.m8n8.x4.trans.shared.b16 {%0,%1,%2,%3}, [%4];"
        : "=r"(r[0]), "=r"(r[1]), "=r"(r[2]), "=r"(r[3]) : "r"(saddr));
}

__device__ __forceinline__ void cp16(uint32_t s, const void* g) {
    asm volatile("cp.async.cg.shared.global [%0], [%1], 16;"
                 :: "r"(s), "l"(g));
}
#define CP_COMMIT() asm volatile("cp.async.commit_group;" ::: "memory")
#define CP_WAIT2()  asm volatile("cp.async.wait_group 2;"  ::: "memory")
#define CP_WAIT1()  asm volatile("cp.async.wait_group 1;"  ::: "memory")
#define CP_WAIT0()  asm volatile("cp.async.wait_group 0;"  ::: "memory")

__device__ __forceinline__ uint32_t pack_h2(float a, float b) {
    __half2 h = __half2{__float2half_rn(a), __float2half_rn(b)};
    return *(uint32_t*)&h;
}

// ---------------------------------------------------------------------------
// fp32 -> fp16 hi/lo split (float4 per thread)
// ---------------------------------------------------------------------------
__global__ __launch_bounds__(256)
void split_kernel(const float* __restrict__ x,
                  __half* __restrict__ hi,
                  __half* __restrict__ lo, int n)
{
    int i = (blockIdx.x * 256 + threadIdx.x) * 4;
    if (i >= n) return;
    float4 v = *(const float4*)(x + i);
    float vv[4] = {v.x, v.y, v.z, v.w};
    __half h[4], l[4];
#pragma unroll
    for (int j = 0; j < 4; j++) {
        h[j] = __float2half_rn(vv[j]);
        l[j] = __float2half_rn(vv[j] - __half2float(h[j]));
    }
    __half2* hp = (__half2*)(hi + i);
    __half2* lp = (__half2*)(lo + i);
    hp[0] = __half2{h[0], h[1]};
    hp[1] = __half2{h[2], h[3]};
    lp[0] = __half2{l[0], l[1]};
    lp[1] = __half2{l[2], l[3]};
}

// ---------------------------------------------------------------------------
// fp16x3 tensor-core GEMM: C = (Ahi+Alo) @ (Bhi+Blo)^T
// HOUT=false: fp32 out (+bias).  HOUT=true: fp16 hi/lo out.
// CTA tile 128x128, BK=32, 3-stage cp.async pipeline, 256 threads.
// ---------------------------------------------------------------------------
#define ASTR   80
#define TILE_B (128 * ASTR)
#define OFF_AH 0
#define OFF_AL (1 * TILE_B)
#define OFF_BH (2 * TILE_B)
#define OFF_BL (3 * TILE_B)
#define BUF_B  (4 * TILE_B)
#define GEMM_SMEM (3 * BUF_B)

template <bool BIAS, bool HOUT>
__global__ __launch_bounds__(256)
void gemm_f16x3(const __half* __restrict__ Ahi,
                const __half* __restrict__ Alo,
                const __half* __restrict__ Bhi,
                const __half* __restrict__ Blo,
                const float* __restrict__ bias,
                float* __restrict__ C,
                __half* __restrict__ Chi,
                __half* __restrict__ Clo, int ldc)
{
    extern __shared__ __align__(128) char smem[];
    const uint32_t sb = smem_to_u32(smem);

    const int tid  = threadIdx.x;
    const int lane = tid & 31;
    const int wid  = tid >> 5;
    const int wm   = wid >> 1;
    const int wn   = wid & 1;
    const int m0   = blockIdx.y * 128;
    const int n0   = blockIdx.x * 128;

    const int lrow0 = tid >> 2;
    const int lrow1 = (tid + 256) >> 2;
    const int lch   = (tid & 3) * 8;

    const __half* gAh = Ahi + (size_t)(m0 + lrow0) * DIMN + lch;
    const __half* gAl = Alo + (size_t)(m0 + lrow0) * DIMN + lch;
    const __half* gBh = Bhi + (size_t)(n0 + lrow0) * DIMN + lch;
    const __half* gBl = Blo + (size_t)(n0 + lrow0) * DIMN + lch;
    const size_t rstep = (size_t)64 * DIMN;
    const uint32_t s0 = (uint32_t)(lrow0 * ASTR + (tid & 3) * 16);
    const uint32_t s1 = (uint32_t)(lrow1 * ASTR + (tid & 3) * 16);

    const uint32_t aByte = (uint32_t)((wm * 32 + (lane & 15)) * ASTR +
                                      (lane >> 4) * 16);
    const uint32_t bByte = (uint32_t)((wn * 64 + ((lane >> 4) << 3) + (lane & 7)) * ASTR +
                                      ((lane >> 3) & 1) * 16);

    float acc[2][8][4];
#pragma unroll
    for (int i = 0; i < 2; i++)
#pragma unroll
        for (int j = 0; j < 8; j++)
#pragma unroll
            for (int c = 0; c < 4; c++) acc[i][j][c] = 0.f;

#pragma unroll
    for (int st = 0; st < 3; st++) {
        const int k0 = st * 32;
        const uint32_t base = sb + st * BUF_B;
        cp16(base + OFF_AH + s0, gAh + k0);
        cp16(base + OFF_AH + s1, gAh + k0 + rstep);
        cp16(base + OFF_AL + s0, gAl + k0);
        cp16(base + OFF_AL + s1, gAl + k0 + rstep);
        cp16(base + OFF_BH + s0, gBh + k0);
        cp16(base + OFF_BH + s1, gBh + k0 + rstep);
        cp16(base + OFF_BL + s0, gBl + k0);
        cp16(base + OFF_BL + s1, gBl + k0 + rstep);
        CP_COMMIT();
    }

    for (int s = 0; s < 32; s++) {
        CP_WAIT2();
        __syncthreads();

        const uint32_t base = sb + (s % 3) * BUF_B;

#pragma unroll
        for (int kk = 0; kk < 2; kk++) {
            uint32_t ah[2][4], al[2][4];
#pragma unroll
            for (int mi = 0; mi < 2; mi++) {
                ldsm_x4(ah[mi], base + OFF_AH + aByte + mi * 16 * ASTR + kk * 32);
                ldsm_x4(al[mi], base + OFF_AL + aByte + mi * 16 * ASTR + kk * 32);
            }
            uint32_t bh[4][4], bl[4][4];
#pragma unroll
            for (int bn = 0; bn < 4; bn++) {
                ldsm_x4(bh[bn], base + OFF_BH + bByte + bn * 16 * ASTR + kk * 32);
                ldsm_x4(bl[bn], base + OFF_BL + bByte + bn * 16 * ASTR + kk * 32);
            }
#pragma unroll
            for (int mi = 0; mi < 2; mi++)
#pragma unroll
                for (int ni = 0; ni < 8; ni++) {
                    const uint32_t* fh = &bh[ni >> 1][(ni & 1) * 2];
                    const uint32_t* fl = &bl[ni >> 1][(ni & 1) * 2];
                    mma16816(acc[mi][ni], ah[mi], fh);
                    mma16816(acc[mi][ni], ah[mi], fl);
                    mma16816(acc[mi][ni], al[mi], fh);
                }
        }

        __syncthreads();
        if (s + 3 < 32) {
            const int k0 = (s + 3) * 32;
            const uint32_t nb = sb + (s % 3) * BUF_B;
            cp16(nb + OFF_AH + s0, gAh + k0);
            cp16(nb + OFF_AH + s1, gAh + k0 + rstep);
            cp16(nb + OFF_AL + s0, gAl + k0);
            cp16(nb + OFF_AL + s1, gAl + k0 + rstep);
            cp16(nb + OFF_BH + s0, gBh + k0);
            cp16(nb + OFF_BH + s1, gBh + k0 + rstep);
            cp16(nb + OFF_BL + s0, gBl + k0);
            cp16(nb + OFF_BL + s1, gBl + k0 + rstep);
        }
        CP_COMMIT();
    }

#pragma unroll
    for (int mi = 0; mi < 2; mi++) {
        const int row = m0 + wm * 32 + mi * 16 + (lane >> 2);
#pragma unroll
        for (int ni = 0; ni < 8; ni++) {
            const int col = n0 + wn * 64 + ni * 8 + ((lane & 3) << 1);
            if (HOUT) {
                float v00 = acc[mi][ni][0], v01 = acc[mi][ni][1];
                float v10 = acc[mi][ni][2], v11 = acc[mi][ni][3];
                __half h00 = __float2half_rn(v00), h01 = __float2half_rn(v01);
                __half h10 = __float2half_rn(v10), h11 = __float2half_rn(v11);
                __half l00 = __float2half_rn(v00 - __half2float(h00));
                __half l01 = __float2half_rn(v01 - __half2float(h01));
                __half l10 = __float2half_rn(v10 - __half2float(h10));
                __half l11 = __float2half_rn(v11 - __half2float(h11));
                *(__half2*)(Chi + (size_t)row * ldc + col)       = __half2{h00, h01};
                *(__half2*)(Clo + (size_t)row * ldc + col)       = __half2{l00, l01};
                *(__half2*)(Chi + (size_t)(row + 8) * ldc + col) = __half2{h10, h11};
                *(__half2*)(Clo + (size_t)(row + 8) * ldc + col) = __half2{l10, l11};
            } else {
                float b0 = 0.f, b1 = 0.f;
                if (BIAS) { b0 = bias[col]; b1 = bias[col + 1]; }
                float2 v0 = make_float2(acc[mi][ni][0] + b0, acc[mi][ni][1] + b1);
                float2 v1 = make_float2(acc[mi][ni][2] + b0, acc[mi][ni][3] + b1);
                *(float2*)(C + (size_t)row * ldc + col)       = v0;
                *(float2*)(C + (size_t)(row + 8) * ldc + col) = v1;
            }
        }
    }
}

// ---------------------------------------------------------------------------
// Tensor-core flash attention.
// CTA: 192 threads (6 warps x 16 q-rows = 96 rows). grid (5, B*H).
// K/V in 64-key blocks, cp.async double buffer. fp16x3 for S and PV.
// ---------------------------------------------------------------------------
#define QROWS 96
#define ATHREADS 192
#define KSTR 144                         // bytes per 64-half row (128+16)
#define KV_PLANE (64 * KSTR)             // 9216
#define KV_STAGE (4 * KV_PLANE)          // 36864  (Khi,Klo,Vhi,Vlo)
#define Q_OFF (2 * KV_STAGE)             // 73728
#define Q_PLANE (QROWS * KSTR)           // 13824
#define ATTN_SMEM (Q_OFF + 2 * Q_PLANE)  // 101376

__global__ __launch_bounds__(ATHREADS, 2)
void attn_mma_kernel(const float* __restrict__ pe,
                     const __half* __restrict__ QKVhi,
                     const __half* __restrict__ QKVlo,
                     __half* __restrict__ Ohi,
                     __half* __restrict__ Olo)
{
    extern __shared__ __align__(128) char smem[];
    const uint32_t sb = smem_to_u32(smem);
    const int tid  = threadIdx.x;
    const int lane = tid & 31;
    const int wid  = tid >> 5;
    const int q0   = blockIdx.x * QROWS;
    const int bh   = blockIdx.y;
    const int b    = bh >> 4;
    const int h    = bh & 15;

    const size_t rowbase = (size_t)b * SEQ;

    // ---- Q load (part of group 0) ----
    {
        const size_t gq = (rowbase + q0) * PLD + h * HD;
        for (int c = tid; c < 2 * QROWS * 8; c += ATHREADS) {
            const int plane = c / (QROWS * 8);
            const int idx = c - plane * (QROWS * 8);
            const int row = idx >> 3, ch = idx & 7;
            const __half* src = (plane ? QKVlo : QKVhi) + gq + (size_t)row * PLD + ch * 8;
            cp16(sb + Q_OFF + plane * Q_PLANE + (uint32_t)(row * KSTR + ch * 16), src);
        }
    }

    // ---- K/V stage loader ----
    auto load_kv = [&](int kb, int st) {
        const int k0 = kb * 64;
        for (int c = tid; c < 2048; c += ATHREADS) {
            const int plane = c >> 9;           // 0 Khi 1 Klo 2 Vhi 3 Vlo
            const int idx = c & 511;
            const int row = idx >> 3, ch = idx & 7;
            int kr = k0 + row;
            if (kr >= SEQ) kr = SEQ - 1;        // clamp; masked via S later
            const __half* base = (plane & 1) ? QKVlo : QKVhi;
            const int coloff = (plane >> 1) ? 2 * DIMN : DIMN;
            const __half* src = base + (rowbase + kr) * PLD + coloff + h * HD + ch * 8;
            cp16(sb + st * KV_STAGE + plane * KV_PLANE + (uint32_t)(row * KSTR + ch * 16), src);
        }
        CP_COMMIT();
    };

    load_kv(0, 0);     // group 0 (Q + kv0)
    load_kv(1, 1);     // group 1

    // fragment addressing
    const uint32_t qrow_byte = (uint32_t)((wid * 16 + (lane & 15)) * KSTR + (lane >> 4) * 16);
    const uint32_t krow_byte = (uint32_t)((((lane >> 4) << 3) + (lane & 7)) * KSTR +
                                          ((lane >> 3) & 1) * 16);
    const uint32_t vrow_byte = (uint32_t)((lane & 15) * KSTR + (lane >> 4) * 16);

    const int r0  = lane >> 2;                 // rows r0, r0+8 within warp tile
    const int c2  = (lane & 3) * 2;
    const int qr  = q0 + wid * 16 + r0;        // global q row (always < SEQ)
    const float* peA = pe + (size_t)qr * SEQ;
    const float* peB = pe + (size_t)(qr + 8) * SEQ;

    float o[8][4];
#pragma unroll
    for (int i = 0; i < 8; i++)
#pragma unroll
        for (int c = 0; c < 4; c++) o[i][c] = 0.f;
    float mrow0 = -INFINITY, mrow1 = -INFINITY;
    float lsum0 = 0.f, lsum1 = 0.f;

    for (int kb = 0; kb < 8; kb++) {
        if (kb < 7) { CP_WAIT1(); } else { CP_WAIT0(); }
        __syncthreads();

        const uint32_t kvbase = sb + (uint32_t)((kb & 1) * KV_STAGE);
        const int k0 = kb * 64;

        // ---- S = Q @ K^T (fp16x3) ----
        float s[8][4];
#pragma unroll
        for (int i = 0; i < 8; i++)
#pragma unroll
            for (int c = 0; c < 4; c++) s[i][c] = 0.f;

#pragma unroll
        for (int ks = 0; ks < 4; ks++) {
            uint32_t qh[4], ql[4];
            ldsm_x4(qh, sb + Q_OFF + qrow_byte + ks * 32);
            ldsm_x4(ql, sb + Q_OFF + Q_PLANE + qrow_byte + ks * 32);
            uint32_t kh[4][4], kl[4][4];
#pragma unroll
            for (int ng = 0; ng < 4; ng++) {
                ldsm_x4(kh[ng], kvbase + 0 * KV_PLANE + krow_byte + ng * 16 * KSTR + ks * 32);
                ldsm_x4(kl[ng], kvbase + 1 * KV_PLANE + krow_byte + ng * 16 * KSTR + ks * 32);
            }
#pragma unroll
            for (int ni = 0; ni < 8; ni++) {
                const uint32_t* fh = &kh[ni >> 1][(ni & 1) * 2];
                const uint32_t* fl = &kl[ni >> 1][(ni & 1) * 2];
                mma16816(s[ni], qh, fh);
                mma16816(s[ni], qh, fl);
                mma16816(s[ni], ql, fh);
            }
        }

        // ---- scale + pe bias + mask ----
#pragma unroll
        for (int ni = 0; ni < 8; ni++) {
            const int kc = k0 + ni * 8 + c2;
            if (kc + 1 < SEQ || kc < SEQ) {   // kc even, SEQ even -> single bool
                float2 pA = *(const float2*)(peA + kc);
                float2 pB = *(const float2*)(peB + kc);
                s[ni][0] = s[ni][0] * ATTN_SCALE + pA.x;
                s[ni][1] = s[ni][1] * ATTN_SCALE + pA.y;
                s[ni][2] = s[ni][2] * ATTN_SCALE + pB.x;
                s[ni][3] = s[ni][3] * ATTN_SCALE + pB.y;
            } else {
                s[ni][0] = -1e30f; s[ni][1] = -1e30f;
                s[ni][2] = -1e30f; s[ni][3] = -1e30f;
            }
        }

        // ---- online softmax ----
        float m0 = -INFINITY, m1 = -INFINITY;
#pragma unroll
        for (int ni = 0; ni < 8; ni++) {
            m0 = fmaxf(m0, fmaxf(s[ni][0], s[ni][1]));
            m1 = fmaxf(m1, fmaxf(s[ni][2], s[ni][3]));
        }
        m0 = fmaxf(m0, __shfl_xor_sync(0xffffffffu, m0, 1));
        m0 = fmaxf(m0, __shfl_xor_sync(0xffffffffu, m0, 2));
        m1 = fmaxf(m1, __shfl_xor_sync(0xffffffffu, m1, 1));
        m1 = fmaxf(m1, __shfl_xor_sync(0xffffffffu, m1, 2));

        const float mn0 = fmaxf(mrow0, m0);
        const float mn1 = fmaxf(mrow1, m1);
        const float f0 = __expf(mrow0 - mn0);
        const float f1 = __expf(mrow1 - mn1);
        mrow0 = mn0; mrow1 = mn1;

        float sum0 = 0.f, sum1 = 0.f;
        uint32_t phi[4][4], plo[4][4];
#pragma unroll
        for (int ks = 0; ks < 4; ks++) {
            const int n0i = 2 * ks, n1i = 2 * ks + 1;
            float p00 = __expf(s[n0i][0] - mn0), p01 = __expf(s[n0i][1] - mn0);
            float p02 = __expf(s[n0i][2] - mn1), p03 = __expf(s[n0i][3] - mn1);
            float p10 = __expf(s[n1i][0] - mn0), p11 = __expf(s[n1i][1] - mn0);
            float p12 = __expf(s[n1i][2] - mn1), p13 = __expf(s[n1i][3] - mn1);
            sum0 += p00 + p01 + p10 + p11;
            sum1 += p02 + p03 + p12 + p13;
            phi[ks][0] = pack_h2(p00, p01);
            phi[ks][1] = pack_h2(p02, p03);
            phi[ks][2] = pack_h2(p10, p11);
            phi[ks][3] = pack_h2(p12, p13);
            __half2 h0 = *(__half2*)&phi[ks][0];
            __half2 h1 = *(__half2*)&phi[ks][1];
            __half2 h2 = *(__half2*)&phi[ks][2];
            __half2 h3 = *(__half2*)&phi[ks][3];
            plo[ks][0] = pack_h2(p00 - __half2float(h0.x), p01 - __half2float(h0.y));
            plo[ks][1] = pack_h2(p02 - __half2float(h1.x), p03 - __half2float(h1.y));
            plo[ks][2] = pack_h2(p10 - __half2float(h2.x), p11 - __half2float(h2.y));
            plo[ks][3] = pack_h2(p12 - __half2float(h3.x), p13 - __half2float(h3.y));
        }
        lsum0 = lsum0 * f0 + sum0;     // cross-lane reduce deferred to end
        lsum1 = lsum1 * f1 + sum1;

#pragma unroll
        for (int ni = 0; ni < 8; ni++) {
            o[ni][0] *= f0; o[ni][1] *= f0;
            o[ni][2] *= f1; o[ni][3] *= f1;
        }

        // ---- O += P @ V (fp16x3) ----
#pragma unroll
        for (int ks = 0; ks < 4; ks++) {
            uint32_t vh[4][4], vl[4][4];
#pragma unroll
            for (int dg = 0; dg < 4; dg++) {
                ldsm_x4_t(vh[dg], kvbase + 2 * KV_PLANE + vrow_byte + ks * 16 * KSTR + dg * 32);
                ldsm_x4_t(vl[dg], kvbase + 3 * KV_PLANE + vrow_byte + ks * 16 * KSTR + dg * 32);
            }
#pragma unroll
            for (int ni = 0; ni < 8; ni++) {
                const uint32_t* fh = &vh[ni >> 1][(ni & 1) * 2];
                const uint32_t* fl = &vl[ni >> 1][(ni & 1) * 2];
                mma16816(o[ni], phi[ks], fh);
                mma16816(o[ni], phi[ks], fl);
                mma16816(o[ni], plo[ks], fh);
            }
        }

        __syncthreads();
        if (kb + 2 < 8) load_kv(kb + 2, kb & 1);
    }

    // ---- finalize: reduce lsum across the 4 lanes of each row ----
    lsum0 += __shfl_xor_sync(0xffffffffu, lsum0, 1);
    lsum0 += __shfl_xor_sync(0xffffffffu, lsum0, 2);
    lsum1 += __shfl_xor_sync(0xffffffffu, lsum1, 1);
    lsum1 += __shfl_xor_sync(0xffffffffu, lsum1, 2);
    const float inv0 = 1.f / lsum0;
    const float inv1 = 1.f / lsum1;

    const size_t orow0 = (rowbase + qr) * DIMN + h * HD;
    const size_t orow1 = (rowbase + qr + 8) * DIMN + h * HD;
#pragma unroll
    for (int ni = 0; ni < 8; ni++) {
        const int d = ni * 8 + c2;
        float v00 = o[ni][0] * inv0, v01 = o[ni][1] * inv0;
        float v10 = o[ni][2] * inv1, v11 = o[ni][3] * inv1;
        __half h00 = __float2half_rn(v00), h01 = __float2half_rn(v01);
        __half h10 = __float2half_rn(v10), h11 = __float2half_rn(v11);
        __half l00 = __float2half_rn(v00 - __half2float(h00));
        __half l01 = __float2half_rn(v01 - __half2float(h01));
        __half l10 = __float2half_rn(v10 - __half2float(h10));
        __half l11 = __float2half_rn(v11 - __half2float(h11));
        *(__half2*)(Ohi + orow0 + d) = __half2{h00, h01};
        *(__half2*)(Olo + orow0 + d) = __half2{l00, l01};
        *(__half2*)(Ohi + orow1 + d) = __half2{h10, h11};
        *(__half2*)(Olo + orow1 + d) = __half2{l10, l11};
    }
}

// ---------------------------------------------------------------------------
extern "C" void kernel_launch(void* const* d_in, const int* in_sizes, int n_in,
                              void* d_out, int out_size)
{
    const float* q  = (const float*)d_in[0];
    const float* Wq = (const float*)d_in[1];
    const float* Wk = (const float*)d_in[2];
    const float* Wv = (const float*)d_in[3];
    const float* pe = (const float*)d_in[4];
    const float* Wo = (const float*)d_in[5];
    const float* bo = (const float*)d_in[6];
    float* out = (float*)d_out;

    __half *QKVhi, *QKVlo, *qhi, *qlo, *Ohi, *Olo, *Wch, *Wcl, *Woh, *Wol;
    cudaGetSymbolAddress((void**)&QKVhi, g_QKVhi);
    cudaGetSymbolAddress((void**)&QKVlo, g_QKVlo);
    cudaGetSymbolAddress((void**)&qhi, g_qhi);
    cudaGetSymbolAddress((void**)&qlo, g_qlo);
    cudaGetSymbolAddress((void**)&Ohi, g_Ohi);
    cudaGetSymbolAddress((void**)&Olo, g_Olo);
    cudaGetSymbolAddress((void**)&Wch, g_Wcat_hi);
    cudaGetSymbolAddress((void**)&Wcl, g_Wcat_lo);
    cudaGetSymbolAddress((void**)&Woh, g_Wo_hi);
    cudaGetSymbolAddress((void**)&Wol, g_Wo_lo);

    const int nq = MROWS * DIMN;
    const int nw = DIMN * DIMN;

    split_kernel<<<nq / 4 / 256, 256>>>(q, qhi, qlo, nq);
    split_kernel<<<nw / 4 / 256, 256>>>(Wq, Wch,          Wcl,          nw);
    split_kernel<<<nw / 4 / 256, 256>>>(Wk, Wch + nw,     Wcl + nw,     nw);
    split_kernel<<<nw / 4 / 256, 256>>>(Wv, Wch + 2 * nw, Wcl + 2 * nw, nw);
    split_kernel<<<nw / 4 / 256, 256>>>(Wo, Woh,          Wol,          nw);

    cudaFuncSetAttribute(gemm_f16x3<false, true>,
                         cudaFuncAttributeMaxDynamicSharedMemorySize, GEMM_SMEM);
    cudaFuncSetAttribute(gemm_f16x3<true, false>,
                         cudaFuncAttributeMaxDynamicSharedMemorySize, GEMM_SMEM);
    cudaFuncSetAttribute(attn_mma_kernel,
                         cudaFuncAttributeMaxDynamicSharedMemorySize, ATTN_SMEM);

    // Fused QKV projection -> fp16 hi/lo [15360, 3072]
    gemm_f16x3<false, true><<<dim3(PLD / 128, MROWS / 128), 256, GEMM_SMEM>>>(
        qhi, qlo, Wch, Wcl, nullptr, nullptr, QKVhi, QKVlo, PLD);

    // Tensor-core flash attention
    attn_mma_kernel<<<dim3(SEQ / QROWS, BATCH * HEADS), ATHREADS, ATTN_SMEM>>>(
        pe, QKVhi, QKVlo, Ohi, Olo);

    // Output projection + bias -> fp32 out
    gemm_f16x3<true, false><<<dim3(DIMN / 128, MROWS / 128), 256, GEMM_SMEM>>>(
        Ohi, Olo, Woh, Wol, bo, out, nullptr, nullptr, DIMN);
}

// round 5
// speedup vs baseline: 3.2086x; 1.0651x over previous
#include <cuda_runtime.h>
#include <cuda_fp16.h>
#include <cstdint>
#include <math.h>

// ---------------------------------------------------------------------------
// Problem constants
// ---------------------------------------------------------------------------
#define BATCH  32
#define SEQ    480
#define DIMN   1024
#define HEADS  16
#define HD     64
#define MROWS  (BATCH * SEQ)        // 15360
#define PLD    3072                 // fused QKV projection row stride
#define ATTN_SCALE 0.125f

// ---------------------------------------------------------------------------
// Device scratch (allocation-free)
// ---------------------------------------------------------------------------
__device__ __half g_QKVhi[(size_t)MROWS * PLD];
__device__ __half g_QKVlo[(size_t)MROWS * PLD];
__device__ __half g_qhi[(size_t)MROWS * DIMN];
__device__ __half g_qlo[(size_t)MROWS * DIMN];
__device__ __half g_Ohi[(size_t)MROWS * DIMN];
__device__ __half g_Olo[(size_t)MROWS * DIMN];
__device__ __half g_Wcat_hi[(size_t)PLD * DIMN];     // [Wq;Wk;Wv]
__device__ __half g_Wcat_lo[(size_t)PLD * DIMN];
__device__ __half g_Wo_hi[(size_t)DIMN * DIMN];
__device__ __half g_Wo_lo[(size_t)DIMN * DIMN];

// ---------------------------------------------------------------------------
// PTX helpers (sm_80-era, arch-portable: mma.sync / ldmatrix / cp.async)
// ---------------------------------------------------------------------------
__device__ __forceinline__ uint32_t smem_to_u32(const void* p) {
    uint32_t a;
    asm("{ .reg .u64 t; cvta.to.shared.u64 t, %1; cvt.u32.u64 %0, t; }"
        : "=r"(a) : "l"(p));
    return a;
}

__device__ __forceinline__ void mma16816(float* d, const uint32_t* a,
                                         const uint32_t* b) {
    asm volatile(
        "mma.sync.aligned.m16n8k16.row.col.f32.f16.f16.f32 "
        "{%0,%1,%2,%3}, {%4,%5,%6,%7}, {%8,%9}, {%0,%1,%2,%3};"
        : "+f"(d[0]), "+f"(d[1]), "+f"(d[2]), "+f"(d[3])
        : "r"(a[0]), "r"(a[1]), "r"(a[2]), "r"(a[3]),
          "r"(b[0]), "r"(b[1]));
}

__device__ __forceinline__ void ldsm_x4(uint32_t* r, uint32_t saddr) {
    asm volatile(
        "ldmatrix.sync.aligned.m8n8.x4.shared.b16 {%0,%1,%2,%3}, [%4];"
        : "=r"(r[0]), "=r"(r[1]), "=r"(r[2]), "=r"(r[3]) : "r"(saddr));
}

__device__ __forceinline__ void ldsm_x4_t(uint32_t* r, uint32_t saddr) {
    asm volatile(
        "ldmatrix.sync.aligned.m8n8.x4.trans.shared.b16 {%0,%1,%2,%3}, [%4];"
        : "=r"(r[0]), "=r"(r[1]), "=r"(r[2]), "=r"(r[3]) : "r"(saddr));
}

__device__ __forceinline__ void cp16(uint32_t s, const void* g) {
    asm volatile("cp.async.cg.shared.global [%0], [%1], 16;"
                 :: "r"(s), "l"(g));
}
#define CP_COMMIT() asm volatile("cp.async.commit_group;" ::: "memory")
#define CP_WAIT2()  asm volatile("cp.async.wait_group 2;"  ::: "memory")
#define CP_WAIT1()  asm volatile("cp.async.wait_group 1;"  ::: "memory")
#define CP_WAIT0()  asm volatile("cp.async.wait_group 0;"  ::: "memory")

__device__ __forceinline__ uint32_t pack_h2(float a, float b) {
    __half2 h = __half2{__float2half_rn(a), __float2half_rn(b)};
    return *(uint32_t*)&h;
}

// ---------------------------------------------------------------------------
// fp32 -> fp16 hi/lo split (float4 per thread)
// ---------------------------------------------------------------------------
__global__ __launch_bounds__(256)
void split_kernel(const float* __restrict__ x,
                  __half* __restrict__ hi,
                  __half* __restrict__ lo, int n)
{
    int i = (blockIdx.x * 256 + threadIdx.x) * 4;
    if (i >= n) return;
    float4 v = *(const float4*)(x + i);
    float vv[4] = {v.x, v.y, v.z, v.w};
    __half h[4], l[4];
#pragma unroll
    for (int j = 0; j < 4; j++) {
        h[j] = __float2half_rn(vv[j]);
        l[j] = __float2half_rn(vv[j] - __half2float(h[j]));
    }
    __half2* hp = (__half2*)(hi + i);
    __half2* lp = (__half2*)(lo + i);
    hp[0] = __half2{h[0], h[1]};
    hp[1] = __half2{h[2], h[3]};
    lp[0] = __half2{l[0], l[1]};
    lp[1] = __half2{l[2], l[3]};
}

// ---------------------------------------------------------------------------
// fp16 tensor-core GEMM: C = A @ B^T with hi/lo error correction.
// CTAs with n0 >= n_x3 run 3 MMAs (full x3); others 2 MMAs (Ah*(Bh+Bl)),
// skipping A_lo loads entirely.
// HOUT=false: fp32 out (+bias).  HOUT=true: fp16 hi/lo out.
// CTA tile 128x128, BK=32, 3-stage cp.async pipeline, 256 threads.
// ---------------------------------------------------------------------------
#define ASTR   80
#define TILE_B (128 * ASTR)
#define OFF_AH 0
#define OFF_AL (1 * TILE_B)
#define OFF_BH (2 * TILE_B)
#define OFF_BL (3 * TILE_B)
#define BUF_B  (4 * TILE_B)
#define GEMM_SMEM (3 * BUF_B)

template <bool BIAS, bool HOUT>
__global__ __launch_bounds__(256)
void gemm_f16x3(const __half* __restrict__ Ahi,
                const __half* __restrict__ Alo,
                const __half* __restrict__ Bhi,
                const __half* __restrict__ Blo,
                const float* __restrict__ bias,
                float* __restrict__ C,
                __half* __restrict__ Chi,
                __half* __restrict__ Clo, int ldc, int n_x3)
{
    extern __shared__ __align__(128) char smem[];
    const uint32_t sb = smem_to_u32(smem);

    const int tid  = threadIdx.x;
    const int lane = tid & 31;
    const int wid  = tid >> 5;
    const int wm   = wid >> 1;
    const int wn   = wid & 1;
    const int m0   = blockIdx.y * 128;
    const int n0   = blockIdx.x * 128;
    const bool do3 = (n0 >= n_x3);

    const int lrow0 = tid >> 2;
    const int lrow1 = (tid + 256) >> 2;
    const int lch   = (tid & 3) * 8;

    const __half* gAh = Ahi + (size_t)(m0 + lrow0) * DIMN + lch;
    const __half* gAl = Alo + (size_t)(m0 + lrow0) * DIMN + lch;
    const __half* gBh = Bhi + (size_t)(n0 + lrow0) * DIMN + lch;
    const __half* gBl = Blo + (size_t)(n0 + lrow0) * DIMN + lch;
    const size_t rstep = (size_t)64 * DIMN;
    const uint32_t s0 = (uint32_t)(lrow0 * ASTR + (tid & 3) * 16);
    const uint32_t s1 = (uint32_t)(lrow1 * ASTR + (tid & 3) * 16);

    const uint32_t aByte = (uint32_t)((wm * 32 + (lane & 15)) * ASTR +
                                      (lane >> 4) * 16);
    const uint32_t bByte = (uint32_t)((wn * 64 + ((lane >> 4) << 3) + (lane & 7)) * ASTR +
                                      ((lane >> 3) & 1) * 16);

    float acc[2][8][4];
#pragma unroll
    for (int i = 0; i < 2; i++)
#pragma unroll
        for (int j = 0; j < 8; j++)
#pragma unroll
            for (int c = 0; c < 4; c++) acc[i][j][c] = 0.f;

#pragma unroll
    for (int st = 0; st < 3; st++) {
        const int k0 = st * 32;
        const uint32_t base = sb + st * BUF_B;
        cp16(base + OFF_AH + s0, gAh + k0);
        cp16(base + OFF_AH + s1, gAh + k0 + rstep);
        if (do3) {
            cp16(base + OFF_AL + s0, gAl + k0);
            cp16(base + OFF_AL + s1, gAl + k0 + rstep);
        }
        cp16(base + OFF_BH + s0, gBh + k0);
        cp16(base + OFF_BH + s1, gBh + k0 + rstep);
        cp16(base + OFF_BL + s0, gBl + k0);
        cp16(base + OFF_BL + s1, gBl + k0 + rstep);
        CP_COMMIT();
    }

    for (int s = 0; s < 32; s++) {
        CP_WAIT2();
        __syncthreads();

        const uint32_t base = sb + (s % 3) * BUF_B;

#pragma unroll
        for (int kk = 0; kk < 2; kk++) {
            uint32_t ah[2][4], al[2][4];
#pragma unroll
            for (int mi = 0; mi < 2; mi++)
                ldsm_x4(ah[mi], base + OFF_AH + aByte + mi * 16 * ASTR + kk * 32);
            if (do3) {
#pragma unroll
                for (int mi = 0; mi < 2; mi++)
                    ldsm_x4(al[mi], base + OFF_AL + aByte + mi * 16 * ASTR + kk * 32);
            }
            uint32_t bh[4][4], bl[4][4];
#pragma unroll
            for (int bn = 0; bn < 4; bn++) {
                ldsm_x4(bh[bn], base + OFF_BH + bByte + bn * 16 * ASTR + kk * 32);
                ldsm_x4(bl[bn], base + OFF_BL + bByte + bn * 16 * ASTR + kk * 32);
            }
#pragma unroll
            for (int mi = 0; mi < 2; mi++)
#pragma unroll
                for (int ni = 0; ni < 8; ni++) {
                    const uint32_t* fh = &bh[ni >> 1][(ni & 1) * 2];
                    const uint32_t* fl = &bl[ni >> 1][(ni & 1) * 2];
                    mma16816(acc[mi][ni], ah[mi], fh);
                    mma16816(acc[mi][ni], ah[mi], fl);
                    if (do3) mma16816(acc[mi][ni], al[mi], fh);
                }
        }

        __syncthreads();
        if (s + 3 < 32) {
            const int k0 = (s + 3) * 32;
            const uint32_t nb = sb + (s % 3) * BUF_B;
            cp16(nb + OFF_AH + s0, gAh + k0);
            cp16(nb + OFF_AH + s1, gAh + k0 + rstep);
            if (do3) {
                cp16(nb + OFF_AL + s0, gAl + k0);
                cp16(nb + OFF_AL + s1, gAl + k0 + rstep);
            }
            cp16(nb + OFF_BH + s0, gBh + k0);
            cp16(nb + OFF_BH + s1, gBh + k0 + rstep);
            cp16(nb + OFF_BL + s0, gBl + k0);
            cp16(nb + OFF_BL + s1, gBl + k0 + rstep);
        }
        CP_COMMIT();
    }

#pragma unroll
    for (int mi = 0; mi < 2; mi++) {
        const int row = m0 + wm * 32 + mi * 16 + (lane >> 2);
#pragma unroll
        for (int ni = 0; ni < 8; ni++) {
            const int col = n0 + wn * 64 + ni * 8 + ((lane & 3) << 1);
            if (HOUT) {
                float v00 = acc[mi][ni][0], v01 = acc[mi][ni][1];
                float v10 = acc[mi][ni][2], v11 = acc[mi][ni][3];
                __half h00 = __float2half_rn(v00), h01 = __float2half_rn(v01);
                __half h10 = __float2half_rn(v10), h11 = __float2half_rn(v11);
                __half l00 = __float2half_rn(v00 - __half2float(h00));
                __half l01 = __float2half_rn(v01 - __half2float(h01));
                __half l10 = __float2half_rn(v10 - __half2float(h10));
                __half l11 = __float2half_rn(v11 - __half2float(h11));
                *(__half2*)(Chi + (size_t)row * ldc + col)       = __half2{h00, h01};
                *(__half2*)(Clo + (size_t)row * ldc + col)       = __half2{l00, l01};
                *(__half2*)(Chi + (size_t)(row + 8) * ldc + col) = __half2{h10, h11};
                *(__half2*)(Clo + (size_t)(row + 8) * ldc + col) = __half2{l10, l11};
            } else {
                float b0 = 0.f, b1 = 0.f;
                if (BIAS) { b0 = bias[col]; b1 = bias[col + 1]; }
                float2 v0 = make_float2(acc[mi][ni][0] + b0, acc[mi][ni][1] + b1);
                float2 v1 = make_float2(acc[mi][ni][2] + b0, acc[mi][ni][3] + b1);
                *(float2*)(C + (size_t)row * ldc + col)       = v0;
                *(float2*)(C + (size_t)(row + 8) * ldc + col) = v1;
            }
        }
    }
}

// ---------------------------------------------------------------------------
// Tensor-core flash attention.
// CTA: 192 threads (6 warps x 16 q-rows = 96 rows). grid (5, B*H).
// K/V in 64-key blocks, cp.async double buffer.
// S = Qh*(Kh+Kl)  (x2, no Q_lo anywhere);  O = Ph*(Vh+Vl)  (x2, no P_lo).
// ---------------------------------------------------------------------------
#define QROWS 96
#define ATHREADS 192
#define KSTR 144                         // bytes per 64-half row (128+16)
#define KV_PLANE (64 * KSTR)             // 9216
#define KV_STAGE (4 * KV_PLANE)          // 36864  (Khi,Klo,Vhi,Vlo)
#define Q_OFF (2 * KV_STAGE)             // 73728
#define Q_PLANE (QROWS * KSTR)           // 13824
#define ATTN_SMEM (Q_OFF + Q_PLANE)      // 87552

__global__ __launch_bounds__(ATHREADS, 2)
void attn_mma_kernel(const float* __restrict__ pe,
                     const __half* __restrict__ QKVhi,
                     const __half* __restrict__ QKVlo,
                     __half* __restrict__ Ohi,
                     __half* __restrict__ Olo)
{
    extern __shared__ __align__(128) char smem[];
    const uint32_t sb = smem_to_u32(smem);
    const int tid  = threadIdx.x;
    const int lane = tid & 31;
    const int wid  = tid >> 5;
    const int q0   = blockIdx.x * QROWS;
    const int bh   = blockIdx.y;
    const int b    = bh >> 4;
    const int h    = bh & 15;

    const size_t rowbase = (size_t)b * SEQ;

    // ---- Q load (hi plane only; part of group 0) ----
    {
        const size_t gq = (rowbase + q0) * PLD + h * HD;
        for (int c = tid; c < QROWS * 8; c += ATHREADS) {
            const int row = c >> 3, ch = c & 7;
            cp16(sb + Q_OFF + (uint32_t)(row * KSTR + ch * 16),
                 QKVhi + gq + (size_t)row * PLD + ch * 8);
        }
    }

    // ---- K/V stage loader ----
    auto load_kv = [&](int kb, int st) {
        const int k0 = kb * 64;
        for (int c = tid; c < 2048; c += ATHREADS) {
            const int plane = c >> 9;           // 0 Khi 1 Klo 2 Vhi 3 Vlo
            const int idx = c & 511;
            const int row = idx >> 3, ch = idx & 7;
            int kr = k0 + row;
            if (kr >= SEQ) kr = SEQ - 1;        // clamp; masked via S later
            const __half* base = (plane & 1) ? QKVlo : QKVhi;
            const int coloff = (plane >> 1) ? 2 * DIMN : DIMN;
            const __half* src = base + (rowbase + kr) * PLD + coloff + h * HD + ch * 8;
            cp16(sb + st * KV_STAGE + plane * KV_PLANE + (uint32_t)(row * KSTR + ch * 16), src);
        }
        CP_COMMIT();
    };

    load_kv(0, 0);     // group 0 (Q + kv0)
    load_kv(1, 1);     // group 1

    // fragment addressing
    const uint32_t qrow_byte = (uint32_t)((wid * 16 + (lane & 15)) * KSTR + (lane >> 4) * 16);
    const uint32_t krow_byte = (uint32_t)((((lane >> 4) << 3) + (lane & 7)) * KSTR +
                                          ((lane >> 3) & 1) * 16);
    const uint32_t vrow_byte = (uint32_t)((lane & 15) * KSTR + (lane >> 4) * 16);

    const int r0  = lane >> 2;                 // rows r0, r0+8 within warp tile
    const int c2  = (lane & 3) * 2;
    const int qr  = q0 + wid * 16 + r0;        // global q row (always < SEQ)
    const float* peA = pe + (size_t)qr * SEQ;
    const float* peB = pe + (size_t)(qr + 8) * SEQ;

    float o[8][4];
#pragma unroll
    for (int i = 0; i < 8; i++)
#pragma unroll
        for (int c = 0; c < 4; c++) o[i][c] = 0.f;
    float mrow0 = -INFINITY, mrow1 = -INFINITY;
    float lsum0 = 0.f, lsum1 = 0.f;

    for (int kb = 0; kb < 8; kb++) {
        if (kb < 7) { CP_WAIT1(); } else { CP_WAIT0(); }
        __syncthreads();

        const uint32_t kvbase = sb + (uint32_t)((kb & 1) * KV_STAGE);
        const int k0 = kb * 64;

        // ---- S = Qh @ (Kh + Kl)^T ----
        float s[8][4];
#pragma unroll
        for (int i = 0; i < 8; i++)
#pragma unroll
            for (int c = 0; c < 4; c++) s[i][c] = 0.f;

#pragma unroll
        for (int ks = 0; ks < 4; ks++) {
            uint32_t qh[4];
            ldsm_x4(qh, sb + Q_OFF + qrow_byte + ks * 32);
            uint32_t kh[4][4], kl[4][4];
#pragma unroll
            for (int ng = 0; ng < 4; ng++) {
                ldsm_x4(kh[ng], kvbase + 0 * KV_PLANE + krow_byte + ng * 16 * KSTR + ks * 32);
                ldsm_x4(kl[ng], kvbase + 1 * KV_PLANE + krow_byte + ng * 16 * KSTR + ks * 32);
            }
#pragma unroll
            for (int ni = 0; ni < 8; ni++) {
                const uint32_t* fh = &kh[ni >> 1][(ni & 1) * 2];
                const uint32_t* fl = &kl[ni >> 1][(ni & 1) * 2];
                mma16816(s[ni], qh, fh);
                mma16816(s[ni], qh, fl);
            }
        }

        // ---- scale + pe bias + mask ----
#pragma unroll
        for (int ni = 0; ni < 8; ni++) {
            const int kc = k0 + ni * 8 + c2;
            if (kc < SEQ) {
                float2 pA = *(const float2*)(peA + kc);
                float2 pB = *(const float2*)(peB + kc);
                s[ni][0] = s[ni][0] * ATTN_SCALE + pA.x;
                s[ni][1] = s[ni][1] * ATTN_SCALE + pA.y;
                s[ni][2] = s[ni][2] * ATTN_SCALE + pB.x;
                s[ni][3] = s[ni][3] * ATTN_SCALE + pB.y;
            } else {
                s[ni][0] = -1e30f; s[ni][1] = -1e30f;
                s[ni][2] = -1e30f; s[ni][3] = -1e30f;
            }
        }

        // ---- online softmax ----
        float m0 = -INFINITY, m1 = -INFINITY;
#pragma unroll
        for (int ni = 0; ni < 8; ni++) {
            m0 = fmaxf(m0, fmaxf(s[ni][0], s[ni][1]));
            m1 = fmaxf(m1, fmaxf(s[ni][2], s[ni][3]));
        }
        m0 = fmaxf(m0, __shfl_xor_sync(0xffffffffu, m0, 1));
        m0 = fmaxf(m0, __shfl_xor_sync(0xffffffffu, m0, 2));
        m1 = fmaxf(m1, __shfl_xor_sync(0xffffffffu, m1, 1));
        m1 = fmaxf(m1, __shfl_xor_sync(0xffffffffu, m1, 2));

        const float mn0 = fmaxf(mrow0, m0);
        const float mn1 = fmaxf(mrow1, m1);
        const float f0 = __expf(mrow0 - mn0);
        const float f1 = __expf(mrow1 - mn1);
        mrow0 = mn0; mrow1 = mn1;

        float sum0 = 0.f, sum1 = 0.f;
        uint32_t phi[4][4];
#pragma unroll
        for (int ks = 0; ks < 4; ks++) {
            const int n0i = 2 * ks, n1i = 2 * ks + 1;
            float p00 = __expf(s[n0i][0] - mn0), p01 = __expf(s[n0i][1] - mn0);
            float p02 = __expf(s[n0i][2] - mn1), p03 = __expf(s[n0i][3] - mn1);
            float p10 = __expf(s[n1i][0] - mn0), p11 = __expf(s[n1i][1] - mn0);
            float p12 = __expf(s[n1i][2] - mn1), p13 = __expf(s[n1i][3] - mn1);
            sum0 += p00 + p01 + p10 + p11;
            sum1 += p02 + p03 + p12 + p13;
            phi[ks][0] = pack_h2(p00, p01);
            phi[ks][1] = pack_h2(p02, p03);
            phi[ks][2] = pack_h2(p10, p11);
            phi[ks][3] = pack_h2(p12, p13);
        }
        lsum0 = lsum0 * f0 + sum0;     // cross-lane reduce deferred to end
        lsum1 = lsum1 * f1 + sum1;

#pragma unroll
        for (int ni = 0; ni < 8; ni++) {
            o[ni][0] *= f0; o[ni][1] *= f0;
            o[ni][2] *= f1; o[ni][3] *= f1;
        }

        // ---- O += Ph @ (Vh + Vl) ----
#pragma unroll
        for (int ks = 0; ks < 4; ks++) {
            uint32_t vh[4][4], vl[4][4];
#pragma unroll
            for (int dg = 0; dg < 4; dg++) {
                ldsm_x4_t(vh[dg], kvbase + 2 * KV_PLANE + vrow_byte + ks * 16 * KSTR + dg * 32);
                ldsm_x4_t(vl[dg], kvbase + 3 * KV_PLANE + vrow_byte + ks * 16 * KSTR + dg * 32);
            }
#pragma unroll
            for (int ni = 0; ni < 8; ni++) {
                const uint32_t* fh = &vh[ni >> 1][(ni & 1) * 2];
                const uint32_t* fl = &vl[ni >> 1][(ni & 1) * 2];
                mma16816(o[ni], phi[ks], fh);
                mma16816(o[ni], phi[ks], fl);
            }
        }

        __syncthreads();
        if (kb + 2 < 8) load_kv(kb + 2, kb & 1);
    }

    // ---- finalize: reduce lsum across the 4 lanes of each row ----
    lsum0 += __shfl_xor_sync(0xffffffffu, lsum0, 1);
    lsum0 += __shfl_xor_sync(0xffffffffu, lsum0, 2);
    lsum1 += __shfl_xor_sync(0xffffffffu, lsum1, 1);
    lsum1 += __shfl_xor_sync(0xffffffffu, lsum1, 2);
    const float inv0 = 1.f / lsum0;
    const float inv1 = 1.f / lsum1;

    const size_t orow0 = (rowbase + qr) * DIMN + h * HD;
    const size_t orow1 = (rowbase + qr + 8) * DIMN + h * HD;
#pragma unroll
    for (int ni = 0; ni < 8; ni++) {
        const int d = ni * 8 + c2;
        float v00 = o[ni][0] * inv0, v01 = o[ni][1] * inv0;
        float v10 = o[ni][2] * inv1, v11 = o[ni][3] * inv1;
        __half h00 = __float2half_rn(v00), h01 = __float2half_rn(v01);
        __half h10 = __float2half_rn(v10), h11 = __float2half_rn(v11);
        __half l00 = __float2half_rn(v00 - __half2float(h00));
        __half l01 = __float2half_rn(v01 - __half2float(h01));
        __half l10 = __float2half_rn(v10 - __half2float(h10));
        __half l11 = __float2half_rn(v11 - __half2float(h11));
        *(__half2*)(Ohi + orow0 + d) = __half2{h00, h01};
        *(__half2*)(Olo + orow0 + d) = __half2{l00, l01};
        *(__half2*)(Ohi + orow1 + d) = __half2{h10, h11};
        *(__half2*)(Olo + orow1 + d) = __half2{l10, l11};
    }
}

// ---------------------------------------------------------------------------
extern "C" void kernel_launch(void* const* d_in, const int* in_sizes, int n_in,
                              void* d_out, int out_size)
{
    const float* q  = (const float*)d_in[0];
    const float* Wq = (const float*)d_in[1];
    const float* Wk = (const float*)d_in[2];
    const float* Wv = (const float*)d_in[3];
    const float* pe = (const float*)d_in[4];
    const float* Wo = (const float*)d_in[5];
    const float* bo = (const float*)d_in[6];
    float* out = (float*)d_out;

    __half *QKVhi, *QKVlo, *qhi, *qlo, *Ohi, *Olo, *Wch, *Wcl, *Woh, *Wol;
    cudaGetSymbolAddress((void**)&QKVhi, g_QKVhi);
    cudaGetSymbolAddress((void**)&QKVlo, g_QKVlo);
    cudaGetSymbolAddress((void**)&qhi, g_qhi);
    cudaGetSymbolAddress((void**)&qlo, g_qlo);
    cudaGetSymbolAddress((void**)&Ohi, g_Ohi);
    cudaGetSymbolAddress((void**)&Olo, g_Olo);
    cudaGetSymbolAddress((void**)&Wch, g_Wcat_hi);
    cudaGetSymbolAddress((void**)&Wcl, g_Wcat_lo);
    cudaGetSymbolAddress((void**)&Woh, g_Wo_hi);
    cudaGetSymbolAddress((void**)&Wol, g_Wo_lo);

    const int nq = MROWS * DIMN;
    const int nw = DIMN * DIMN;

    split_kernel<<<nq / 4 / 256, 256>>>(q, qhi, qlo, nq);
    split_kernel<<<nw / 4 / 256, 256>>>(Wq, Wch,          Wcl,          nw);
    split_kernel<<<nw / 4 / 256, 256>>>(Wk, Wch + nw,     Wcl + nw,     nw);
    split_kernel<<<nw / 4 / 256, 256>>>(Wv, Wch + 2 * nw, Wcl + 2 * nw, nw);
    split_kernel<<<nw / 4 / 256, 256>>>(Wo, Woh,          Wol,          nw);

    cudaFuncSetAttribute(gemm_f16x3<false, true>,
                         cudaFuncAttributeMaxDynamicSharedMemorySize, GEMM_SMEM);
    cudaFuncSetAttribute(gemm_f16x3<true, false>,
                         cudaFuncAttributeMaxDynamicSharedMemorySize, GEMM_SMEM);
    cudaFuncSetAttribute(attn_mma_kernel,
                         cudaFuncAttributeMaxDynamicSharedMemorySize, ATTN_SMEM);

    // Fused QKV projection -> fp16 hi/lo [15360, 3072].
    // Q/K columns (n0 < 2048): x2 MMAs; V columns (n0 >= 2048): x3.
    gemm_f16x3<false, true><<<dim3(PLD / 128, MROWS / 128), 256, GEMM_SMEM>>>(
        qhi, qlo, Wch, Wcl, nullptr, nullptr, QKVhi, QKVlo, PLD, 2048);

    // Tensor-core flash attention
    attn_mma_kernel<<<dim3(SEQ / QROWS, BATCH * HEADS), ATHREADS, ATTN_SMEM>>>(
        pe, QKVhi, QKVlo, Ohi, Olo);

    // Output projection + bias -> fp32 out (full x3)
    gemm_f16x3<true, false><<<dim3(DIMN / 128, MROWS / 128), 256, GEMM_SMEM>>>(
        Ohi, Olo, Woh, Wol, bo, out, nullptr, nullptr, DIMN, 0);
}

// round 6
// speedup vs baseline: 4.9738x; 1.5501x over previous
#include <cuda_runtime.h>
#include <cuda_fp16.h>
#include <cstdint>
#include <math.h>

// ---------------------------------------------------------------------------
// Problem constants
// ---------------------------------------------------------------------------
#define BATCH  32
#define SEQ    480
#define DIMN   1024
#define HEADS  16
#define HD     64
#define MROWS  (BATCH * SEQ)        // 15360
#define PLD    3072                 // fused QKV projection row stride
#define ATTN_SCALE 0.125f

// ---------------------------------------------------------------------------
// Device scratch (allocation-free)
// ---------------------------------------------------------------------------
__device__ __half g_QKVhi[(size_t)MROWS * PLD];
__device__ __half g_QKVlo[(size_t)MROWS * PLD];   // only K/V columns ever written/read
__device__ __half g_qhi[(size_t)MROWS * DIMN];
__device__ __half g_Ohi[(size_t)MROWS * DIMN];
__device__ __half g_Wcat_hi[(size_t)PLD * DIMN];  // [Wq;Wk;Wv]
__device__ __half g_Wcat_lo[(size_t)PLD * DIMN];
__device__ __half g_Wo_hi[(size_t)DIMN * DIMN];
__device__ __half g_Wo_lo[(size_t)DIMN * DIMN];

// ---------------------------------------------------------------------------
// PTX helpers (sm_80-era, arch-portable: mma.sync / ldmatrix / cp.async)
// ---------------------------------------------------------------------------
__device__ __forceinline__ uint32_t smem_to_u32(const void* p) {
    uint32_t a;
    asm("{ .reg .u64 t; cvta.to.shared.u64 t, %1; cvt.u32.u64 %0, t; }"
        : "=r"(a) : "l"(p));
    return a;
}

__device__ __forceinline__ void mma16816(float* d, const uint32_t* a,
                                         const uint32_t* b) {
    asm volatile(
        "mma.sync.aligned.m16n8k16.row.col.f32.f16.f16.f32 "
        "{%0,%1,%2,%3}, {%4,%5,%6,%7}, {%8,%9}, {%0,%1,%2,%3};"
        : "+f"(d[0]), "+f"(d[1]), "+f"(d[2]), "+f"(d[3])
        : "r"(a[0]), "r"(a[1]), "r"(a[2]), "r"(a[3]),
          "r"(b[0]), "r"(b[1]));
}

__device__ __forceinline__ void ldsm_x4(uint32_t* r, uint32_t saddr) {
    asm volatile(
        "ldmatrix.sync.aligned.m8n8.x4.shared.b16 {%0,%1,%2,%3}, [%4];"
        : "=r"(r[0]), "=r"(r[1]), "=r"(r[2]), "=r"(r[3]) : "r"(saddr));
}

__device__ __forceinline__ void ldsm_x4_t(uint32_t* r, uint32_t saddr) {
    asm volatile(
        "ldmatrix.sync.aligned.m8n8.x4.trans.shared.b16 {%0,%1,%2,%3}, [%4];"
        : "=r"(r[0]), "=r"(r[1]), "=r"(r[2]), "=r"(r[3]) : "r"(saddr));
}

__device__ __forceinline__ void cp16(uint32_t s, const void* g) {
    asm volatile("cp.async.cg.shared.global [%0], [%1], 16;"
                 :: "r"(s), "l"(g));
}
#define CP_COMMIT() asm volatile("cp.async.commit_group;" ::: "memory")
#define CP_WAIT2()  asm volatile("cp.async.wait_group 2;"  ::: "memory")
#define CP_WAIT1()  asm volatile("cp.async.wait_group 1;"  ::: "memory")
#define CP_WAIT0()  asm volatile("cp.async.wait_group 0;"  ::: "memory")

__device__ __forceinline__ uint32_t pack_h2(float a, float b) {
    __half2 h = __half2{__float2half_rn(a), __float2half_rn(b)};
    return *(uint32_t*)&h;
}

// ---------------------------------------------------------------------------
// fp32 -> fp16 hi/lo split, and hi-only convert (float4 per thread)
// ---------------------------------------------------------------------------
__global__ __launch_bounds__(256)
void split_kernel(const float* __restrict__ x,
                  __half* __restrict__ hi,
                  __half* __restrict__ lo, int n)
{
    int i = (blockIdx.x * 256 + threadIdx.x) * 4;
    if (i >= n) return;
    float4 v = *(const float4*)(x + i);
    float vv[4] = {v.x, v.y, v.z, v.w};
    __half h[4], l[4];
#pragma unroll
    for (int j = 0; j < 4; j++) {
        h[j] = __float2half_rn(vv[j]);
        l[j] = __float2half_rn(vv[j] - __half2float(h[j]));
    }
    __half2* hp = (__half2*)(hi + i);
    __half2* lp = (__half2*)(lo + i);
    hp[0] = __half2{h[0], h[1]};
    hp[1] = __half2{h[2], h[3]};
    lp[0] = __half2{l[0], l[1]};
    lp[1] = __half2{l[2], l[3]};
}

__global__ __launch_bounds__(256)
void tohalf_kernel(const float* __restrict__ x,
                   __half* __restrict__ hi, int n)
{
    int i = (blockIdx.x * 256 + threadIdx.x) * 4;
    if (i >= n) return;
    float4 v = *(const float4*)(x + i);
    __half2* hp = (__half2*)(hi + i);
    hp[0] = __half2{__float2half_rn(v.x), __float2half_rn(v.y)};
    hp[1] = __half2{__float2half_rn(v.z), __float2half_rn(v.w)};
}

// ---------------------------------------------------------------------------
// fp16x2 tensor-core GEMM: C = Ah @ (Bh + Bl)^T  (+bias)
// HOUT=false: fp32 out (+bias).  HOUT=true: fp16 hi/lo out; lo stores only
// for columns >= lo_min (consumers never read Q-column lo).
// CTA tile 128x128, BK=32, 3-stage cp.async pipeline, 256 thr, 2 CTAs/SM.
// ---------------------------------------------------------------------------
#define ASTR   80
#define TILE_B (128 * ASTR)              // 10240
#define OFF_AH 0
#define OFF_BH (1 * TILE_B)
#define OFF_BL (2 * TILE_B)
#define BUF_B  (3 * TILE_B)              // 30720 per stage
#define GEMM_SMEM (3 * BUF_B)            // 92160

template <bool BIAS, bool HOUT>
__global__ __launch_bounds__(256, 2)
void gemm_f16x2(const __half* __restrict__ Ahi,
                const __half* __restrict__ Bhi,
                const __half* __restrict__ Blo,
                const float* __restrict__ bias,
                float* __restrict__ C,
                __half* __restrict__ Chi,
                __half* __restrict__ Clo, int ldc, int lo_min)
{
    extern __shared__ __align__(128) char smem[];
    const uint32_t sb = smem_to_u32(smem);

    const int tid  = threadIdx.x;
    const int lane = tid & 31;
    const int wid  = tid >> 5;
    const int wm   = wid >> 1;
    const int wn   = wid & 1;
    const int m0   = blockIdx.y * 128;
    const int n0   = blockIdx.x * 128;

    const int lrow0 = tid >> 2;
    const int lch   = (tid & 3) * 8;

    const __half* gAh = Ahi + (size_t)(m0 + lrow0) * DIMN + lch;
    const __half* gBh = Bhi + (size_t)(n0 + lrow0) * DIMN + lch;
    const __half* gBl = Blo + (size_t)(n0 + lrow0) * DIMN + lch;
    const size_t rstep = (size_t)64 * DIMN;
    const uint32_t s0 = (uint32_t)(lrow0 * ASTR + (tid & 3) * 16);
    const uint32_t s1 = s0 + (uint32_t)(64 * ASTR);

    const uint32_t aByte = (uint32_t)((wm * 32 + (lane & 15)) * ASTR +
                                      (lane >> 4) * 16);
    const uint32_t bByte = (uint32_t)((wn * 64 + ((lane >> 4) << 3) + (lane & 7)) * ASTR +
                                      ((lane >> 3) & 1) * 16);

    float acc[2][8][4];
#pragma unroll
    for (int i = 0; i < 2; i++)
#pragma unroll
        for (int j = 0; j < 8; j++)
#pragma unroll
            for (int c = 0; c < 4; c++) acc[i][j][c] = 0.f;

#pragma unroll
    for (int st = 0; st < 3; st++) {
        const int k0 = st * 32;
        const uint32_t base = sb + st * BUF_B;
        cp16(base + OFF_AH + s0, gAh + k0);
        cp16(base + OFF_AH + s1, gAh + k0 + rstep);
        cp16(base + OFF_BH + s0, gBh + k0);
        cp16(base + OFF_BH + s1, gBh + k0 + rstep);
        cp16(base + OFF_BL + s0, gBl + k0);
        cp16(base + OFF_BL + s1, gBl + k0 + rstep);
        CP_COMMIT();
    }

    for (int s = 0; s < 32; s++) {
        CP_WAIT2();
        __syncthreads();

        const uint32_t base = sb + (s % 3) * BUF_B;

#pragma unroll
        for (int kk = 0; kk < 2; kk++) {
            uint32_t ah[2][4];
#pragma unroll
            for (int mi = 0; mi < 2; mi++)
                ldsm_x4(ah[mi], base + OFF_AH + aByte + mi * 16 * ASTR + kk * 32);
            uint32_t bh[4][4], bl[4][4];
#pragma unroll
            for (int bn = 0; bn < 4; bn++) {
                ldsm_x4(bh[bn], base + OFF_BH + bByte + bn * 16 * ASTR + kk * 32);
                ldsm_x4(bl[bn], base + OFF_BL + bByte + bn * 16 * ASTR + kk * 32);
            }
#pragma unroll
            for (int mi = 0; mi < 2; mi++)
#pragma unroll
                for (int ni = 0; ni < 8; ni++) {
                    const uint32_t* fh = &bh[ni >> 1][(ni & 1) * 2];
                    const uint32_t* fl = &bl[ni >> 1][(ni & 1) * 2];
                    mma16816(acc[mi][ni], ah[mi], fh);
                    mma16816(acc[mi][ni], ah[mi], fl);
                }
        }

        __syncthreads();
        if (s + 3 < 32) {
            const int k0 = (s + 3) * 32;
            const uint32_t nb = sb + (s % 3) * BUF_B;
            cp16(nb + OFF_AH + s0, gAh + k0);
            cp16(nb + OFF_AH + s1, gAh + k0 + rstep);
            cp16(nb + OFF_BH + s0, gBh + k0);
            cp16(nb + OFF_BH + s1, gBh + k0 + rstep);
            cp16(nb + OFF_BL + s0, gBl + k0);
            cp16(nb + OFF_BL + s1, gBl + k0 + rstep);
        }
        CP_COMMIT();
    }

    const bool wlo = HOUT && (n0 >= lo_min);
#pragma unroll
    for (int mi = 0; mi < 2; mi++) {
        const int row = m0 + wm * 32 + mi * 16 + (lane >> 2);
#pragma unroll
        for (int ni = 0; ni < 8; ni++) {
            const int col = n0 + wn * 64 + ni * 8 + ((lane & 3) << 1);
            if (HOUT) {
                float v00 = acc[mi][ni][0], v01 = acc[mi][ni][1];
                float v10 = acc[mi][ni][2], v11 = acc[mi][ni][3];
                __half h00 = __float2half_rn(v00), h01 = __float2half_rn(v01);
                __half h10 = __float2half_rn(v10), h11 = __float2half_rn(v11);
                *(__half2*)(Chi + (size_t)row * ldc + col)       = __half2{h00, h01};
                *(__half2*)(Chi + (size_t)(row + 8) * ldc + col) = __half2{h10, h11};
                if (wlo) {
                    __half l00 = __float2half_rn(v00 - __half2float(h00));
                    __half l01 = __float2half_rn(v01 - __half2float(h01));
                    __half l10 = __float2half_rn(v10 - __half2float(h10));
                    __half l11 = __float2half_rn(v11 - __half2float(h11));
                    *(__half2*)(Clo + (size_t)row * ldc + col)       = __half2{l00, l01};
                    *(__half2*)(Clo + (size_t)(row + 8) * ldc + col) = __half2{l10, l11};
                }
            } else {
                float b0 = 0.f, b1 = 0.f;
                if (BIAS) { b0 = bias[col]; b1 = bias[col + 1]; }
                float2 v0 = make_float2(acc[mi][ni][0] + b0, acc[mi][ni][1] + b1);
                float2 v1 = make_float2(acc[mi][ni][2] + b0, acc[mi][ni][3] + b1);
                *(float2*)(C + (size_t)row * ldc + col)       = v0;
                *(float2*)(C + (size_t)(row + 8) * ldc + col) = v1;
            }
        }
    }
}

// ---------------------------------------------------------------------------
// Tensor-core flash attention.
// CTA: 192 threads (6 warps x 16 q-rows = 96 rows). grid (5, B*H).
// K/V in 64-key blocks, cp.async double buffer.
// S = Qh*(Kh+Kl);  O = Ph*(Vh+Vl).  Output: fp16 hi only.
// ---------------------------------------------------------------------------
#define QROWS 96
#define ATHREADS 192
#define KSTR 144                         // bytes per 64-half row (128+16)
#define KV_PLANE (64 * KSTR)             // 9216
#define KV_STAGE (4 * KV_PLANE)          // 36864  (Khi,Klo,Vhi,Vlo)
#define Q_OFF (2 * KV_STAGE)             // 73728
#define Q_PLANE (QROWS * KSTR)           // 13824
#define ATTN_SMEM (Q_OFF + Q_PLANE)      // 87552

__global__ __launch_bounds__(ATHREADS, 2)
void attn_mma_kernel(const float* __restrict__ pe,
                     const __half* __restrict__ QKVhi,
                     const __half* __restrict__ QKVlo,
                     __half* __restrict__ Ohi)
{
    extern __shared__ __align__(128) char smem[];
    const uint32_t sb = smem_to_u32(smem);
    const int tid  = threadIdx.x;
    const int lane = tid & 31;
    const int wid  = tid >> 5;
    const int q0   = blockIdx.x * QROWS;
    const int bh   = blockIdx.y;
    const int b    = bh >> 4;
    const int h    = bh & 15;

    const size_t rowbase = (size_t)b * SEQ;

    // ---- Q load (hi plane only; part of group 0) ----
    {
        const size_t gq = (rowbase + q0) * PLD + h * HD;
        for (int c = tid; c < QROWS * 8; c += ATHREADS) {
            const int row = c >> 3, ch = c & 7;
            cp16(sb + Q_OFF + (uint32_t)(row * KSTR + ch * 16),
                 QKVhi + gq + (size_t)row * PLD + ch * 8);
        }
    }

    // ---- K/V stage loader ----
    auto load_kv = [&](int kb, int st) {
        const int k0 = kb * 64;
        for (int c = tid; c < 2048; c += ATHREADS) {
            const int plane = c >> 9;           // 0 Khi 1 Klo 2 Vhi 3 Vlo
            const int idx = c & 511;
            const int row = idx >> 3, ch = idx & 7;
            int kr = k0 + row;
            if (kr >= SEQ) kr = SEQ - 1;        // clamp; masked via S later
            const __half* base = (plane & 1) ? QKVlo : QKVhi;
            const int coloff = (plane >> 1) ? 2 * DIMN : DIMN;
            const __half* src = base + (rowbase + kr) * PLD + coloff + h * HD + ch * 8;
            cp16(sb + st * KV_STAGE + plane * KV_PLANE + (uint32_t)(row * KSTR + ch * 16), src);
        }
        CP_COMMIT();
    };

    load_kv(0, 0);     // group 0 (Q + kv0)
    load_kv(1, 1);     // group 1

    // fragment addressing
    const uint32_t qrow_byte = (uint32_t)((wid * 16 + (lane & 15)) * KSTR + (lane >> 4) * 16);
    const uint32_t krow_byte = (uint32_t)((((lane >> 4) << 3) + (lane & 7)) * KSTR +
                                          ((lane >> 3) & 1) * 16);
    const uint32_t vrow_byte = (uint32_t)((lane & 15) * KSTR + (lane >> 4) * 16);

    const int r0  = lane >> 2;
    const int c2  = (lane & 3) * 2;
    const int qr  = q0 + wid * 16 + r0;        // global q row (always < SEQ)
    const float* peA = pe + (size_t)qr * SEQ;
    const float* peB = pe + (size_t)(qr + 8) * SEQ;

    float o[8][4];
#pragma unroll
    for (int i = 0; i < 8; i++)
#pragma unroll
        for (int c = 0; c < 4; c++) o[i][c] = 0.f;
    float mrow0 = -INFINITY, mrow1 = -INFINITY;
    float lsum0 = 0.f, lsum1 = 0.f;

    for (int kb = 0; kb < 8; kb++) {
        if (kb < 7) { CP_WAIT1(); } else { CP_WAIT0(); }
        __syncthreads();

        const uint32_t kvbase = sb + (uint32_t)((kb & 1) * KV_STAGE);
        const int k0 = kb * 64;

        // ---- S = Qh @ (Kh + Kl)^T ----
        float s[8][4];
#pragma unroll
        for (int i = 0; i < 8; i++)
#pragma unroll
            for (int c = 0; c < 4; c++) s[i][c] = 0.f;

#pragma unroll
        for (int ks = 0; ks < 4; ks++) {
            uint32_t qh[4];
            ldsm_x4(qh, sb + Q_OFF + qrow_byte + ks * 32);
            uint32_t kh[4][4], kl[4][4];
#pragma unroll
            for (int ng = 0; ng < 4; ng++) {
                ldsm_x4(kh[ng], kvbase + 0 * KV_PLANE + krow_byte + ng * 16 * KSTR + ks * 32);
                ldsm_x4(kl[ng], kvbase + 1 * KV_PLANE + krow_byte + ng * 16 * KSTR + ks * 32);
            }
#pragma unroll
            for (int ni = 0; ni < 8; ni++) {
                const uint32_t* fh = &kh[ni >> 1][(ni & 1) * 2];
                const uint32_t* fl = &kl[ni >> 1][(ni & 1) * 2];
                mma16816(s[ni], qh, fh);
                mma16816(s[ni], qh, fl);
            }
        }

        // ---- scale + pe bias + mask ----
#pragma unroll
        for (int ni = 0; ni < 8; ni++) {
            const int kc = k0 + ni * 8 + c2;
            if (kc < SEQ) {
                float2 pA = *(const float2*)(peA + kc);
                float2 pB = *(const float2*)(peB + kc);
                s[ni][0] = s[ni][0] * ATTN_SCALE + pA.x;
                s[ni][1] = s[ni][1] * ATTN_SCALE + pA.y;
                s[ni][2] = s[ni][2] * ATTN_SCALE + pB.x;
                s[ni][3] = s[ni][3] * ATTN_SCALE + pB.y;
            } else {
                s[ni][0] = -1e30f; s[ni][1] = -1e30f;
                s[ni][2] = -1e30f; s[ni][3] = -1e30f;
            }
        }

        // ---- online softmax ----
        float m0 = -INFINITY, m1 = -INFINITY;
#pragma unroll
        for (int ni = 0; ni < 8; ni++) {
            m0 = fmaxf(m0, fmaxf(s[ni][0], s[ni][1]));
            m1 = fmaxf(m1, fmaxf(s[ni][2], s[ni][3]));
        }
        m0 = fmaxf(m0, __shfl_xor_sync(0xffffffffu, m0, 1));
        m0 = fmaxf(m0, __shfl_xor_sync(0xffffffffu, m0, 2));
        m1 = fmaxf(m1, __shfl_xor_sync(0xffffffffu, m1, 1));
        m1 = fmaxf(m1, __shfl_xor_sync(0xffffffffu, m1, 2));

        const float mn0 = fmaxf(mrow0, m0);
        const float mn1 = fmaxf(mrow1, m1);
        const float f0 = __expf(mrow0 - mn0);
        const float f1 = __expf(mrow1 - mn1);
        mrow0 = mn0; mrow1 = mn1;

        float sum0 = 0.f, sum1 = 0.f;
        uint32_t phi[4][4];
#pragma unroll
        for (int ks = 0; ks < 4; ks++) {
            const int n0i = 2 * ks, n1i = 2 * ks + 1;
            float p00 = __expf(s[n0i][0] - mn0), p01 = __expf(s[n0i][1] - mn0);
            float p02 = __expf(s[n0i][2] - mn1), p03 = __expf(s[n0i][3] - mn1);
            float p10 = __expf(s[n1i][0] - mn0), p11 = __expf(s[n1i][1] - mn0);
            float p12 = __expf(s[n1i][2] - mn1), p13 = __expf(s[n1i][3] - mn1);
            sum0 += p00 + p01 + p10 + p11;
            sum1 += p02 + p03 + p12 + p13;
            phi[ks][0] = pack_h2(p00, p01);
            phi[ks][1] = pack_h2(p02, p03);
            phi[ks][2] = pack_h2(p10, p11);
            phi[ks][3] = pack_h2(p12, p13);
        }
        lsum0 = lsum0 * f0 + sum0;     // cross-lane reduce deferred to end
        lsum1 = lsum1 * f1 + sum1;

#pragma unroll
        for (int ni = 0; ni < 8; ni++) {
            o[ni][0] *= f0; o[ni][1] *= f0;
            o[ni][2] *= f1; o[ni][3] *= f1;
        }

        // ---- O += Ph @ (Vh + Vl) ----
#pragma unroll
        for (int ks = 0; ks < 4; ks++) {
            uint32_t vh[4][4], vl[4][4];
#pragma unroll
            for (int dg = 0; dg < 4; dg++) {
                ldsm_x4_t(vh[dg], kvbase + 2 * KV_PLANE + vrow_byte + ks * 16 * KSTR + dg * 32);
                ldsm_x4_t(vl[dg], kvbase + 3 * KV_PLANE + vrow_byte + ks * 16 * KSTR + dg * 32);
            }
#pragma unroll
            for (int ni = 0; ni < 8; ni++) {
                const uint32_t* fh = &vh[ni >> 1][(ni & 1) * 2];
                const uint32_t* fl = &vl[ni >> 1][(ni & 1) * 2];
                mma16816(o[ni], phi[ks], fh);
                mma16816(o[ni], phi[ks], fl);
            }
        }

        __syncthreads();
        if (kb + 2 < 8) load_kv(kb + 2, kb & 1);
    }

    // ---- finalize: reduce lsum across the 4 lanes of each row ----
    lsum0 += __shfl_xor_sync(0xffffffffu, lsum0, 1);
    lsum0 += __shfl_xor_sync(0xffffffffu, lsum0, 2);
    lsum1 += __shfl_xor_sync(0xffffffffu, lsum1, 1);
    lsum1 += __shfl_xor_sync(0xffffffffu, lsum1, 2);
    const float inv0 = 1.f / lsum0;
    const float inv1 = 1.f / lsum1;

    const size_t orow0 = (rowbase + qr) * DIMN + h * HD;
    const size_t orow1 = (rowbase + qr + 8) * DIMN + h * HD;
#pragma unroll
    for (int ni = 0; ni < 8; ni++) {
        const int d = ni * 8 + c2;
        *(__half2*)(Ohi + orow0 + d) =
            __half2{__float2half_rn(o[ni][0] * inv0), __float2half_rn(o[ni][1] * inv0)};
        *(__half2*)(Ohi + orow1 + d) =
            __half2{__float2half_rn(o[ni][2] * inv1), __float2half_rn(o[ni][3] * inv1)};
    }
}

// ---------------------------------------------------------------------------
extern "C" void kernel_launch(void* const* d_in, const int* in_sizes, int n_in,
                              void* d_out, int out_size)
{
    const float* q  = (const float*)d_in[0];
    const float* Wq = (const float*)d_in[1];
    const float* Wk = (const float*)d_in[2];
    const float* Wv = (const float*)d_in[3];
    const float* pe = (const float*)d_in[4];
    const float* Wo = (const float*)d_in[5];
    const float* bo = (const float*)d_in[6];
    float* out = (float*)d_out;

    __half *QKVhi, *QKVlo, *qhi, *Ohi, *Wch, *Wcl, *Woh, *Wol;
    cudaGetSymbolAddress((void**)&QKVhi, g_QKVhi);
    cudaGetSymbolAddress((void**)&QKVlo, g_QKVlo);
    cudaGetSymbolAddress((void**)&qhi, g_qhi);
    cudaGetSymbolAddress((void**)&Ohi, g_Ohi);
    cudaGetSymbolAddress((void**)&Wch, g_Wcat_hi);
    cudaGetSymbolAddress((void**)&Wcl, g_Wcat_lo);
    cudaGetSymbolAddress((void**)&Woh, g_Wo_hi);
    cudaGetSymbolAddress((void**)&Wol, g_Wo_lo);

    const int nq = MROWS * DIMN;
    const int nw = DIMN * DIMN;

    tohalf_kernel<<<nq / 4 / 256, 256>>>(q, qhi, nq);
    split_kernel<<<nw / 4 / 256, 256>>>(Wq, Wch,          Wcl,          nw);
    split_kernel<<<nw / 4 / 256, 256>>>(Wk, Wch + nw,     Wcl + nw,     nw);
    split_kernel<<<nw / 4 / 256, 256>>>(Wv, Wch + 2 * nw, Wcl + 2 * nw, nw);
    split_kernel<<<nw / 4 / 256, 256>>>(Wo, Woh,          Wol,          nw);

    cudaFuncSetAttribute(gemm_f16x2<false, true>,
                         cudaFuncAttributeMaxDynamicSharedMemorySize, GEMM_SMEM);
    cudaFuncSetAttribute(gemm_f16x2<true, false>,
                         cudaFuncAttributeMaxDynamicSharedMemorySize, GEMM_SMEM);
    cudaFuncSetAttribute(attn_mma_kernel,
                         cudaFuncAttributeMaxDynamicSharedMemorySize, ATTN_SMEM);

    // Fused QKV projection -> fp16 hi (+lo for K/V columns only)
    gemm_f16x2<false, true><<<dim3(PLD / 128, MROWS / 128), 256, GEMM_SMEM>>>(
        qhi, Wch, Wcl, nullptr, nullptr, QKVhi, QKVlo, PLD, DIMN);

    // Tensor-core flash attention -> fp16 hi O
    attn_mma_kernel<<<dim3(SEQ / QROWS, BATCH * HEADS), ATHREADS, ATTN_SMEM>>>(
        pe, QKVhi, QKVlo, Ohi);

    // Output projection + bias -> fp32 out (x2)
    gemm_f16x2<true, false><<<dim3(DIMN / 128, MROWS / 128), 256, GEMM_SMEM>>>(
        Ohi, Woh, Wol, bo, out, nullptr, nullptr, DIMN, 0);
}